// round 3
// baseline (speedup 1.0000x reference)
#include <cuda_runtime.h>
#include <math.h>

#define NHEADS 8
#define DMODEL 1024
#define DHEAD  128
#define KFDIM  3072
#define NSENT  2048
#define NKNOW  8192

// Scratch for per-head projections (no cudaMalloc allowed).
__device__ float g_S[NHEADS * NSENT * DHEAD];   // 8 MB
__device__ float g_K[NHEADS * NKNOW * DHEAD];   // 32 MB

// ---------------------------------------------------------------------------
// Generic batched tiled SGEMM.
//   C[z][m, n] = scale * sum_k A[z][m, k] * B(z, k, n)  (+ bias[z][n])
//   A: row-major, lda. B: if !TRANS_B row-major [K,N] (ldb = row stride);
//      if TRANS_B, B is stored [N,K] row-major (ldb = row stride) and we
//      read B(k,n) = B[n*ldb + k].
//   C element: C + z*strideC + m*ldc + n.
// Requires M%128==0, N%128==0, K%8==0, pointers 16B aligned, lda/ldb/ldc %4==0.
// ---------------------------------------------------------------------------
#define BM 128
#define BN 128
#define BK 8

template<bool TRANS_B, bool HAS_BIAS>
__global__ __launch_bounds__(256)
void sgemm_kernel(const float* __restrict__ A, const float* __restrict__ B,
                  const float* __restrict__ bias, float* __restrict__ C,
                  int M, int N, int K,
                  int lda, int ldb, int ldc,
                  long strideA, long strideB, long strideBias, long strideC,
                  float scale)
{
    __shared__ float As[BK][BM];
    __shared__ float Bs[BK][BN];

    const int t  = threadIdx.x;          // 0..255
    const int z  = blockIdx.z;
    const int bm0 = blockIdx.y * BM;
    const int bn0 = blockIdx.x * BN;

    const float* Ap = A + (size_t)z * strideA;
    const float* Bp = B + (size_t)z * strideB;
    float*       Cp = C + (size_t)z * strideC;

    // A tile loader: 128 rows x 8 cols, one float4 per thread along k
    const int a_row = t >> 1;            // 0..127
    const int a_col = (t & 1) << 2;      // 0 or 4
    // B tile loader (non-trans): 8 rows x 128 cols, float4 along n
    const int b_row = t >> 5;            // 0..7
    const int b_col = (t & 31) << 2;     // 0..124
    // B tile loader (trans): 128 n-rows, float4 along k
    const int tb_n  = t >> 1;            // 0..127
    const int tb_k  = (t & 1) << 2;      // 0 or 4

    const int tx = t & 15;               // n micro-tile
    const int ty = t >> 4;               // m micro-tile

    float acc[8][8];
#pragma unroll
    for (int i = 0; i < 8; i++)
#pragma unroll
        for (int j = 0; j < 8; j++) acc[i][j] = 0.f;

    for (int k0 = 0; k0 < K; k0 += BK) {
        // --- stage A (transposed into smem: As[k][m]) ---
        float4 av = *(const float4*)(Ap + (size_t)(bm0 + a_row) * lda + k0 + a_col);
        As[a_col + 0][a_row] = av.x;
        As[a_col + 1][a_row] = av.y;
        As[a_col + 2][a_row] = av.z;
        As[a_col + 3][a_row] = av.w;

        // --- stage B (Bs[k][n]) ---
        if (!TRANS_B) {
            float4 bv = *(const float4*)(Bp + (size_t)(k0 + b_row) * ldb + bn0 + b_col);
            *(float4*)&Bs[b_row][b_col] = bv;
        } else {
            float4 bv = *(const float4*)(Bp + (size_t)(bn0 + tb_n) * ldb + k0 + tb_k);
            Bs[tb_k + 0][tb_n] = bv.x;
            Bs[tb_k + 1][tb_n] = bv.y;
            Bs[tb_k + 2][tb_n] = bv.z;
            Bs[tb_k + 3][tb_n] = bv.w;
        }
        __syncthreads();

#pragma unroll
        for (int kk = 0; kk < BK; kk++) {
            float ar[8], br[8];
            *(float4*)(ar)     = *(const float4*)&As[kk][ty * 8];
            *(float4*)(ar + 4) = *(const float4*)&As[kk][ty * 8 + 4];
            *(float4*)(br)     = *(const float4*)&Bs[kk][tx * 8];
            *(float4*)(br + 4) = *(const float4*)&Bs[kk][tx * 8 + 4];
#pragma unroll
            for (int i = 0; i < 8; i++)
#pragma unroll
                for (int j = 0; j < 8; j++)
                    acc[i][j] = fmaf(ar[i], br[j], acc[i][j]);
        }
        __syncthreads();
    }

    // --- epilogue ---
    float bv[8];
    if (HAS_BIAS) {
        const float* bp = bias + (size_t)z * strideBias + bn0 + tx * 8;
#pragma unroll
        for (int j = 0; j < 8; j++) bv[j] = bp[j];
    }
#pragma unroll
    for (int i = 0; i < 8; i++) {
        size_t m = (size_t)(bm0 + ty * 8 + i);
        float* crow = Cp + m * (size_t)ldc + bn0 + tx * 8;
        float4 o0, o1;
        o0.x = acc[i][0] * scale; o0.y = acc[i][1] * scale;
        o0.z = acc[i][2] * scale; o0.w = acc[i][3] * scale;
        o1.x = acc[i][4] * scale; o1.y = acc[i][5] * scale;
        o1.z = acc[i][6] * scale; o1.w = acc[i][7] * scale;
        if (HAS_BIAS) {
            o0.x += bv[0]; o0.y += bv[1]; o0.z += bv[2]; o0.w += bv[3];
            o1.x += bv[4]; o1.y += bv[5]; o1.z += bv[6]; o1.w += bv[7];
        }
        *(float4*)(crow)     = o0;
        *(float4*)(crow + 4) = o1;
    }
}

// ---------------------------------------------------------------------------
// Column softmax over the sentence axis (axis n) of attn[h][n][m], in place.
// One thread per (h, m) column: 2048 strided (coalesced-across-threads) reads
// for online max+sum, then one read+write pass to normalize.
// ---------------------------------------------------------------------------
__global__ void softmax_cols_kernel(float* __restrict__ attn)
{
    const int h = blockIdx.y;
    const int m = blockIdx.x * blockDim.x + threadIdx.x;   // 0..NKNOW-1
    float* p = attn + (size_t)h * NSENT * NKNOW + m;

    float mx = -INFINITY;
    float sum = 0.f;
    for (int n = 0; n < NSENT; n++) {
        float v = p[(size_t)n * NKNOW];
        if (v > mx) {
            sum = sum * __expf(mx - v) + 1.f;
            mx = v;
        } else {
            sum += __expf(v - mx);
        }
    }
    const float inv = 1.f / sum;
    for (int n = 0; n < NSENT; n++) {
        size_t idx = (size_t)n * NKNOW;
        p[idx] = __expf(p[idx] - mx) * inv;
    }
}

// ---------------------------------------------------------------------------
// Launch: S proj -> K proj -> scores -> softmax -> fused
// Output layout: [attn (H*NS*NK floats) | fused (NS*H*KFDIM floats)]
// ---------------------------------------------------------------------------
extern "C" void kernel_launch(void* const* d_in, const int* in_sizes, int n_in,
                              void* d_out, int out_size)
{
    const float* sentences = (const float*)d_in[0];   // [NS, D]
    const float* knowledge = (const float*)d_in[1];   // [NK, KFDIM]
    const float* w_s       = (const float*)d_in[2];   // [H, D, DH]
    const float* b_s       = (const float*)d_in[3];   // [H, DH]
    const float* w_k       = (const float*)d_in[4];   // [H, KFDIM, DH]
    const float* b_k       = (const float*)d_in[5];   // [H, DH]

    float* attn  = (float*)d_out;                               // [H, NS, NK]
    float* fused = (float*)d_out + (size_t)NHEADS * NSENT * NKNOW; // [NS, H*KFDIM]

    float* Sbuf = nullptr;
    float* Kbuf = nullptr;
    cudaGetSymbolAddress((void**)&Sbuf, g_S);
    cudaGetSymbolAddress((void**)&Kbuf, g_K);

    // 1) S = sentences @ w_s[h] + b_s[h]  -> g_S [H, NS, DH]
    {
        dim3 grid(DHEAD / BN, NSENT / BM, NHEADS);
        sgemm_kernel<false, true><<<grid, 256>>>(
            sentences, w_s, b_s, Sbuf,
            NSENT, DHEAD, DMODEL,
            DMODEL, DHEAD, DHEAD,
            0L, (long)DMODEL * DHEAD, (long)DHEAD, (long)NSENT * DHEAD,
            1.0f);
    }
    // 2) K = knowledge @ w_k[h] + b_k[h]  -> g_K [H, NK, DH]
    {
        dim3 grid(DHEAD / BN, NKNOW / BM, NHEADS);
        sgemm_kernel<false, true><<<grid, 256>>>(
            knowledge, w_k, b_k, Kbuf,
            NKNOW, DHEAD, KFDIM,
            KFDIM, DHEAD, DHEAD,
            0L, (long)KFDIM * DHEAD, (long)DHEAD, (long)NKNOW * DHEAD,
            1.0f);
    }
    // 3) scores[h] = (S[h] @ K[h]^T) / sqrt(DH) -> attn region (pre-softmax)
    {
        dim3 grid(NKNOW / BN, NSENT / BM, NHEADS);
        const float scale = 0.08838834764831845f;  // 1/sqrt(128)
        sgemm_kernel<true, false><<<grid, 256>>>(
            Sbuf, Kbuf, nullptr, attn,
            NSENT, NKNOW, DHEAD,
            DHEAD, DHEAD, NKNOW,
            (long)NSENT * DHEAD, (long)NKNOW * DHEAD, 0L, (long)NSENT * NKNOW,
            scale);
    }
    // 4) softmax over the sentence axis, in place
    {
        dim3 grid(NKNOW / 256, NHEADS);
        softmax_cols_kernel<<<grid, 256>>>(attn);
    }
    // 5) fused[n, h*KFDIM + f] = attn[h] @ knowledge
    {
        dim3 grid(KFDIM / BN, NSENT / BM, NHEADS);
        sgemm_kernel<false, false><<<grid, 256>>>(
            attn, knowledge, nullptr, fused,
            NSENT, KFDIM, NKNOW,
            NKNOW, KFDIM, NHEADS * KFDIM,
            (long)NSENT * NKNOW, 0L, 0L, (long)KFDIM,
            1.0f);
    }
}

// round 5
// speedup vs baseline: 2.7933x; 2.7933x over previous
#include <cuda_runtime.h>
#include <math.h>
#include <stdint.h>

#define NHEADS 8
#define DMODEL 1024
#define DHEAD  128
#define KFDIM  3072
#define NSENT  2048
#define NKNOW  8192

// Scratch (no cudaMalloc allowed).
__device__ float g_S[NHEADS * NSENT * DHEAD];   // 8 MB
__device__ float g_K[NHEADS * NKNOW * DHEAD];   // 32 MB

// ===========================================================================
// fp32 tiled SGEMM (stages 1-3)
// ===========================================================================
#define BM 128
#define BN 128
#define BK 8

template<bool TRANS_B, bool HAS_BIAS>
__global__ __launch_bounds__(256)
void sgemm_kernel(const float* __restrict__ A, const float* __restrict__ B,
                  const float* __restrict__ bias, float* __restrict__ C,
                  int M, int N, int K,
                  int lda, int ldb, int ldc,
                  long strideA, long strideB, long strideBias, long strideC,
                  float scale)
{
    __shared__ float As[BK][BM];
    __shared__ float Bs[BK][BN];

    const int t  = threadIdx.x;
    const int z  = blockIdx.z;
    const int bm0 = blockIdx.y * BM;
    const int bn0 = blockIdx.x * BN;

    const float* Ap = A + (size_t)z * strideA;
    const float* Bp = B + (size_t)z * strideB;
    float*       Cp = C + (size_t)z * strideC;

    const int a_row = t >> 1;
    const int a_col = (t & 1) << 2;
    const int b_row = t >> 5;
    const int b_col = (t & 31) << 2;
    const int tb_n  = t >> 1;
    const int tb_k  = (t & 1) << 2;

    const int tx = t & 15;
    const int ty = t >> 4;

    float acc[8][8];
#pragma unroll
    for (int i = 0; i < 8; i++)
#pragma unroll
        for (int j = 0; j < 8; j++) acc[i][j] = 0.f;

    for (int k0 = 0; k0 < K; k0 += BK) {
        float4 av = *(const float4*)(Ap + (size_t)(bm0 + a_row) * lda + k0 + a_col);
        As[a_col + 0][a_row] = av.x;
        As[a_col + 1][a_row] = av.y;
        As[a_col + 2][a_row] = av.z;
        As[a_col + 3][a_row] = av.w;

        if (!TRANS_B) {
            float4 bv = *(const float4*)(Bp + (size_t)(k0 + b_row) * ldb + bn0 + b_col);
            *(float4*)&Bs[b_row][b_col] = bv;
        } else {
            float4 bv = *(const float4*)(Bp + (size_t)(bn0 + tb_n) * ldb + k0 + tb_k);
            Bs[tb_k + 0][tb_n] = bv.x;
            Bs[tb_k + 1][tb_n] = bv.y;
            Bs[tb_k + 2][tb_n] = bv.z;
            Bs[tb_k + 3][tb_n] = bv.w;
        }
        __syncthreads();

#pragma unroll
        for (int kk = 0; kk < BK; kk++) {
            float ar[8], br[8];
            *(float4*)(ar)     = *(const float4*)&As[kk][ty * 8];
            *(float4*)(ar + 4) = *(const float4*)&As[kk][ty * 8 + 4];
            *(float4*)(br)     = *(const float4*)&Bs[kk][tx * 8];
            *(float4*)(br + 4) = *(const float4*)&Bs[kk][tx * 8 + 4];
#pragma unroll
            for (int i = 0; i < 8; i++)
#pragma unroll
                for (int j = 0; j < 8; j++)
                    acc[i][j] = fmaf(ar[i], br[j], acc[i][j]);
        }
        __syncthreads();
    }

    float bv[8];
    if (HAS_BIAS) {
        const float* bp = bias + (size_t)z * strideBias + bn0 + tx * 8;
#pragma unroll
        for (int j = 0; j < 8; j++) bv[j] = bp[j];
    }
#pragma unroll
    for (int i = 0; i < 8; i++) {
        size_t m = (size_t)(bm0 + ty * 8 + i);
        float* crow = Cp + m * (size_t)ldc + bn0 + tx * 8;
        float4 o0, o1;
        o0.x = acc[i][0] * scale; o0.y = acc[i][1] * scale;
        o0.z = acc[i][2] * scale; o0.w = acc[i][3] * scale;
        o1.x = acc[i][4] * scale; o1.y = acc[i][5] * scale;
        o1.z = acc[i][6] * scale; o1.w = acc[i][7] * scale;
        if (HAS_BIAS) {
            o0.x += bv[0]; o0.y += bv[1]; o0.z += bv[2]; o0.w += bv[3];
            o1.x += bv[4]; o1.y += bv[5]; o1.z += bv[6]; o1.w += bv[7];
        }
        *(float4*)(crow)     = o0;
        *(float4*)(crow + 4) = o1;
    }
}

// ===========================================================================
// Column softmax over sentence axis, in place
// ===========================================================================
__global__ void softmax_cols_kernel(float* __restrict__ attn)
{
    const int h = blockIdx.y;
    const int m = blockIdx.x * blockDim.x + threadIdx.x;
    float* p = attn + (size_t)h * NSENT * NKNOW + m;

    float mx = -INFINITY;
    float sum = 0.f;
    for (int n = 0; n < NSENT; n++) {
        float v = p[(size_t)n * NKNOW];
        if (v > mx) {
            sum = sum * __expf(mx - v) + 1.f;
            mx = v;
        } else {
            sum += __expf(v - mx);
        }
    }
    const float inv = 1.f / sum;
    for (int n = 0; n < NSENT; n++) {
        size_t idx = (size_t)n * NKNOW;
        p[idx] = __expf(p[idx] - mx) * inv;
    }
}

// ===========================================================================
// tf32 mma.sync GEMM (NN):  fused[h-block] = attn[h] @ knowledge
//   A: attn per head [NSENT, NKNOW] row-major (k contiguous)
//   B: knowledge [NKNOW, KFDIM] row-major (n contiguous)
//   CTA 128x128x32, 8 warps (2x4), warp tile 64x32, mma m16n8k8,
//   cp.async double-buffered smem. A smem stride 36, B stride 136
//   (both fragment-load bank-conflict-free).
// ===========================================================================
#define MTK 32
#define SA_STRIDE 36
#define SB_STRIDE 136
#define SA_BUF (128 * SA_STRIDE)       // 4608 floats
#define SB_BUF (MTK * SB_STRIDE)       // 4352 floats
#define MMA_SMEM ((2 * SA_BUF + 2 * SB_BUF) * 4)   // 71680 bytes

__device__ __forceinline__ uint32_t f2tf32(float x) {
    uint32_t r;
    asm("cvt.rna.tf32.f32 %0, %1;" : "=r"(r) : "f"(x));
    return r;
}
__device__ __forceinline__ void mma_tf32(float* d, const uint32_t* a, const uint32_t* b) {
    asm volatile(
        "mma.sync.aligned.m16n8k8.row.col.f32.tf32.tf32.f32 "
        "{%0,%1,%2,%3}, {%4,%5,%6,%7}, {%8,%9}, {%0,%1,%2,%3};"
        : "+f"(d[0]), "+f"(d[1]), "+f"(d[2]), "+f"(d[3])
        : "r"(a[0]), "r"(a[1]), "r"(a[2]), "r"(a[3]), "r"(b[0]), "r"(b[1]));
}
__device__ __forceinline__ void cp_async16(uint32_t dst, const void* src) {
    asm volatile("cp.async.cg.shared.global [%0], [%1], 16;" :: "r"(dst), "l"(src));
}

__global__ void __launch_bounds__(256, 2)
fused_mma_tf32(const float* __restrict__ A, const float* __restrict__ B,
               float* __restrict__ C)
{
    extern __shared__ float sm[];
    float* sA = sm;                  // 2 x [128][36]
    float* sB = sm + 2 * SA_BUF;     // 2 x [32][136]

    const int tid  = threadIdx.x;
    const int lane = tid & 31;
    const int wid  = tid >> 5;
    const int wm   = wid >> 2;       // 0..1
    const int wn   = wid & 3;        // 0..3
    const int z    = blockIdx.z;
    const int m0   = blockIdx.y * 128;
    const int n0   = blockIdx.x * 128;

    const float* Ap = A + (size_t)z * NSENT * NKNOW + (size_t)m0 * NKNOW;
    const float* Bp = B + n0;

    // loader indices
    const int ar  = tid >> 3;                 // A rows ar, ar+32, ar+64, ar+96
    const int ac  = (tid & 7) << 2;           // A col (k) in [0,32)
    const int br  = tid >> 5;                 // B rows br, +8, +16, +24 (k)
    const int bc  = (tid & 31) << 2;          // B col (n) in [0,128)

    uint32_t sA_u32 = (uint32_t)__cvta_generic_to_shared(sA);
    uint32_t sB_u32 = (uint32_t)__cvta_generic_to_shared(sB);

    float acc[4][4][4];
#pragma unroll
    for (int mt = 0; mt < 4; mt++)
#pragma unroll
        for (int nt = 0; nt < 4; nt++)
#pragma unroll
            for (int r = 0; r < 4; r++) acc[mt][nt][r] = 0.f;

    const int NT = NKNOW / MTK;   // 256

    // ---- issue tile loads for ktile kt into buffer b ----
    auto issue = [&](int kt, int b) {
        const float* abase = Ap + (size_t)kt * MTK;
#pragma unroll
        for (int p = 0; p < 4; p++) {
            int row = ar + 32 * p;
            cp_async16(sA_u32 + (uint32_t)(b * SA_BUF + row * SA_STRIDE + ac) * 4,
                       abase + (size_t)row * NKNOW + ac);
        }
        const float* bbase = Bp + (size_t)(kt * MTK) * KFDIM;
#pragma unroll
        for (int p = 0; p < 4; p++) {
            int row = br + 8 * p;
            cp_async16(sB_u32 + (uint32_t)(b * SB_BUF + row * SB_STRIDE + bc) * 4,
                       bbase + (size_t)row * KFDIM + bc);
        }
    };

    issue(0, 0);
    asm volatile("cp.async.commit_group;" ::: "memory");

    for (int kt = 0; kt < NT; kt++) {
        if (kt + 1 < NT) {
            issue(kt + 1, (kt + 1) & 1);
            asm volatile("cp.async.commit_group;" ::: "memory");
            asm volatile("cp.async.wait_group 1;" ::: "memory");
        } else {
            asm volatile("cp.async.wait_group 0;" ::: "memory");
        }
        __syncthreads();

        const float* tA = sA + (kt & 1) * SA_BUF;
        const float* tB = sB + (kt & 1) * SB_BUF;

#pragma unroll
        for (int ks = 0; ks < 4; ks++) {
            const int kk = ks * 8 + (lane & 3);
            // B fragments for 4 n-tiles
            uint32_t bf[4][2];
            const int nn = wn * 32 + (lane >> 2);
#pragma unroll
            for (int nt = 0; nt < 4; nt++) {
                bf[nt][0] = f2tf32(tB[kk * SB_STRIDE + nn + nt * 8]);
                bf[nt][1] = f2tf32(tB[(kk + 4) * SB_STRIDE + nn + nt * 8]);
            }
#pragma unroll
            for (int mt = 0; mt < 4; mt++) {
                const int rr = wm * 64 + mt * 16 + (lane >> 2);
                uint32_t af[4];
                af[0] = f2tf32(tA[rr * SA_STRIDE + kk]);
                af[1] = f2tf32(tA[(rr + 8) * SA_STRIDE + kk]);
                af[2] = f2tf32(tA[rr * SA_STRIDE + kk + 4]);
                af[3] = f2tf32(tA[(rr + 8) * SA_STRIDE + kk + 4]);
#pragma unroll
                for (int nt = 0; nt < 4; nt++)
                    mma_tf32(acc[mt][nt], af, bf[nt]);
            }
        }
        __syncthreads();
    }

    // ---- epilogue: fused[m, z*KFDIM + n], row stride H*KFDIM ----
    const int ldc = NHEADS * KFDIM;
#pragma unroll
    for (int mt = 0; mt < 4; mt++) {
        const int r = m0 + wm * 64 + mt * 16 + (lane >> 2);
#pragma unroll
        for (int nt = 0; nt < 4; nt++) {
            const int c = z * KFDIM + n0 + wn * 32 + nt * 8 + ((lane & 3) << 1);
            float2 v0 = make_float2(acc[mt][nt][0], acc[mt][nt][1]);
            float2 v1 = make_float2(acc[mt][nt][2], acc[mt][nt][3]);
            *(float2*)(C + (size_t)r * ldc + c)        = v0;
            *(float2*)(C + (size_t)(r + 8) * ldc + c)  = v1;
        }
    }
}

// ===========================================================================
// Host side
// ===========================================================================
extern "C" void kernel_launch(void* const* d_in, const int* in_sizes, int n_in,
                              void* d_out, int out_size)
{
    const float* sentences = (const float*)d_in[0];
    const float* knowledge = (const float*)d_in[1];
    const float* w_s       = (const float*)d_in[2];
    const float* b_s       = (const float*)d_in[3];
    const float* w_k       = (const float*)d_in[4];
    const float* b_k       = (const float*)d_in[5];

    float* attn  = (float*)d_out;
    float* fused = (float*)d_out + (size_t)NHEADS * NSENT * NKNOW;

    float *Sbuf = nullptr, *Kbuf = nullptr;
    cudaGetSymbolAddress((void**)&Sbuf, g_S);
    cudaGetSymbolAddress((void**)&Kbuf, g_K);

    // 1) S projection
    {
        dim3 grid(DHEAD / BN, NSENT / BM, NHEADS);
        sgemm_kernel<false, true><<<grid, 256>>>(
            sentences, w_s, b_s, Sbuf,
            NSENT, DHEAD, DMODEL, DMODEL, DHEAD, DHEAD,
            0L, (long)DMODEL * DHEAD, (long)DHEAD, (long)NSENT * DHEAD, 1.0f);
    }
    // 2) K projection
    {
        dim3 grid(DHEAD / BN, NKNOW / BM, NHEADS);
        sgemm_kernel<false, true><<<grid, 256>>>(
            knowledge, w_k, b_k, Kbuf,
            NKNOW, DHEAD, KFDIM, KFDIM, DHEAD, DHEAD,
            0L, (long)KFDIM * DHEAD, (long)DHEAD, (long)NKNOW * DHEAD, 1.0f);
    }
    // 3) scores
    {
        dim3 grid(NKNOW / BN, NSENT / BM, NHEADS);
        const float scale = 0.08838834764831845f;
        sgemm_kernel<true, false><<<grid, 256>>>(
            Sbuf, Kbuf, nullptr, attn,
            NSENT, NKNOW, DHEAD, DHEAD, DHEAD, NKNOW,
            (long)NSENT * DHEAD, (long)NKNOW * DHEAD, 0L, (long)NSENT * NKNOW, scale);
    }
    // 4) softmax
    {
        dim3 grid(NKNOW / 256, NHEADS);
        softmax_cols_kernel<<<grid, 256>>>(attn);
    }
    // 5) fused GEMM on tensor cores (tf32 mma.sync)
    {
        static bool attr_set = false;
        if (!attr_set) {
            cudaFuncSetAttribute(fused_mma_tf32,
                                 cudaFuncAttributeMaxDynamicSharedMemorySize, MMA_SMEM);
            attr_set = true;
        }
        dim3 grid(KFDIM / 128, NSENT / 128, NHEADS);   // (24, 16, 8)
        fused_mma_tf32<<<grid, 256, MMA_SMEM>>>(attn, knowledge, fused);
    }
}

// round 6
// speedup vs baseline: 3.1083x; 1.1128x over previous
#include <cuda_runtime.h>
#include <math.h>
#include <stdint.h>

#define NHEADS 8
#define DMODEL 1024
#define DHEAD  128
#define KFDIM  3072
#define NSENT  2048
#define NKNOW  8192

// Scratch (no cudaMalloc allowed).
__device__ float g_S[NHEADS * NSENT * DHEAD];   // 8 MB
__device__ float g_K[NHEADS * NKNOW * DHEAD];   // 32 MB
__device__ float g_colsum[NHEADS * NKNOW];      // 256 KB (exp column sums)

// ===========================================================================
// fp32 tiled SGEMM (projections)
// ===========================================================================
#define BM 128
#define BN 128
#define BK 8

template<bool TRANS_B, bool HAS_BIAS>
__global__ __launch_bounds__(256)
void sgemm_kernel(const float* __restrict__ A, const float* __restrict__ B,
                  const float* __restrict__ bias, float* __restrict__ C,
                  int M, int N, int K,
                  int lda, int ldb, int ldc,
                  long strideA, long strideB, long strideBias, long strideC,
                  float scale)
{
    __shared__ float As[BK][BM];
    __shared__ float Bs[BK][BN];

    const int t  = threadIdx.x;
    const int z  = blockIdx.z;
    const int bm0 = blockIdx.y * BM;
    const int bn0 = blockIdx.x * BN;

    const float* Ap = A + (size_t)z * strideA;
    const float* Bp = B + (size_t)z * strideB;
    float*       Cp = C + (size_t)z * strideC;

    const int a_row = t >> 1;
    const int a_col = (t & 1) << 2;
    const int b_row = t >> 5;
    const int b_col = (t & 31) << 2;
    const int tb_n  = t >> 1;
    const int tb_k  = (t & 1) << 2;

    const int tx = t & 15;
    const int ty = t >> 4;

    float acc[8][8];
#pragma unroll
    for (int i = 0; i < 8; i++)
#pragma unroll
        for (int j = 0; j < 8; j++) acc[i][j] = 0.f;

    for (int k0 = 0; k0 < K; k0 += BK) {
        float4 av = *(const float4*)(Ap + (size_t)(bm0 + a_row) * lda + k0 + a_col);
        As[a_col + 0][a_row] = av.x;
        As[a_col + 1][a_row] = av.y;
        As[a_col + 2][a_row] = av.z;
        As[a_col + 3][a_row] = av.w;

        if (!TRANS_B) {
            float4 bv = *(const float4*)(Bp + (size_t)(k0 + b_row) * ldb + bn0 + b_col);
            *(float4*)&Bs[b_row][b_col] = bv;
        } else {
            float4 bv = *(const float4*)(Bp + (size_t)(bn0 + tb_n) * ldb + k0 + tb_k);
            Bs[tb_k + 0][tb_n] = bv.x;
            Bs[tb_k + 1][tb_n] = bv.y;
            Bs[tb_k + 2][tb_n] = bv.z;
            Bs[tb_k + 3][tb_n] = bv.w;
        }
        __syncthreads();

#pragma unroll
        for (int kk = 0; kk < BK; kk++) {
            float ar[8], br[8];
            *(float4*)(ar)     = *(const float4*)&As[kk][ty * 8];
            *(float4*)(ar + 4) = *(const float4*)&As[kk][ty * 8 + 4];
            *(float4*)(br)     = *(const float4*)&Bs[kk][tx * 8];
            *(float4*)(br + 4) = *(const float4*)&Bs[kk][tx * 8 + 4];
#pragma unroll
            for (int i = 0; i < 8; i++)
#pragma unroll
                for (int j = 0; j < 8; j++)
                    acc[i][j] = fmaf(ar[i], br[j], acc[i][j]);
        }
        __syncthreads();
    }

    float bv[8];
    if (HAS_BIAS) {
        const float* bp = bias + (size_t)z * strideBias + bn0 + tx * 8;
#pragma unroll
        for (int j = 0; j < 8; j++) bv[j] = bp[j];
    }
#pragma unroll
    for (int i = 0; i < 8; i++) {
        size_t m = (size_t)(bm0 + ty * 8 + i);
        float* crow = Cp + m * (size_t)ldc + bn0 + tx * 8;
        float4 o0, o1;
        o0.x = acc[i][0] * scale; o0.y = acc[i][1] * scale;
        o0.z = acc[i][2] * scale; o0.w = acc[i][3] * scale;
        o1.x = acc[i][4] * scale; o1.y = acc[i][5] * scale;
        o1.z = acc[i][6] * scale; o1.w = acc[i][7] * scale;
        if (HAS_BIAS) {
            o0.x += bv[0]; o0.y += bv[1]; o0.z += bv[2]; o0.w += bv[3];
            o1.x += bv[4]; o1.y += bv[5]; o1.z += bv[6]; o1.w += bv[7];
        }
        *(float4*)(crow)     = o0;
        *(float4*)(crow + 4) = o1;
    }
}

// ===========================================================================
// Scores GEMM (TN, fp32) with fused exp epilogue + column-sum reduction.
//   C[z][n][m] = exp( scale * S[z][n,:] . K[z][m,:] ), colsum[z][m] += partials
// ===========================================================================
__global__ __launch_bounds__(256)
void scores_exp_kernel(const float* __restrict__ A, const float* __restrict__ B,
                       float* __restrict__ C, float scale)
{
    __shared__ float As[BK][BM];
    __shared__ float Bs[BK][BN];
    __shared__ float red[16][128];

    const int t  = threadIdx.x;
    const int z  = blockIdx.z;
    const int bm0 = blockIdx.y * BM;
    const int bn0 = blockIdx.x * BN;

    const float* Ap = A + (size_t)z * NSENT * DHEAD;   // S[z] [NSENT, DHEAD]
    const float* Bp = B + (size_t)z * NKNOW * DHEAD;   // K[z] [NKNOW, DHEAD]
    float*       Cp = C + (size_t)z * NSENT * NKNOW;

    const int a_row = t >> 1;
    const int a_col = (t & 1) << 2;
    const int tb_n  = t >> 1;
    const int tb_k  = (t & 1) << 2;
    const int tx = t & 15;
    const int ty = t >> 4;

    float acc[8][8];
#pragma unroll
    for (int i = 0; i < 8; i++)
#pragma unroll
        for (int j = 0; j < 8; j++) acc[i][j] = 0.f;

    for (int k0 = 0; k0 < DHEAD; k0 += BK) {
        float4 av = *(const float4*)(Ap + (size_t)(bm0 + a_row) * DHEAD + k0 + a_col);
        As[a_col + 0][a_row] = av.x;
        As[a_col + 1][a_row] = av.y;
        As[a_col + 2][a_row] = av.z;
        As[a_col + 3][a_row] = av.w;
        float4 bv = *(const float4*)(Bp + (size_t)(bn0 + tb_n) * DHEAD + k0 + tb_k);
        Bs[tb_k + 0][tb_n] = bv.x;
        Bs[tb_k + 1][tb_n] = bv.y;
        Bs[tb_k + 2][tb_n] = bv.z;
        Bs[tb_k + 3][tb_n] = bv.w;
        __syncthreads();
#pragma unroll
        for (int kk = 0; kk < BK; kk++) {
            float ar[8], br[8];
            *(float4*)(ar)     = *(const float4*)&As[kk][ty * 8];
            *(float4*)(ar + 4) = *(const float4*)&As[kk][ty * 8 + 4];
            *(float4*)(br)     = *(const float4*)&Bs[kk][tx * 8];
            *(float4*)(br + 4) = *(const float4*)&Bs[kk][tx * 8 + 4];
#pragma unroll
            for (int i = 0; i < 8; i++)
#pragma unroll
                for (int j = 0; j < 8; j++)
                    acc[i][j] = fmaf(ar[i], br[j], acc[i][j]);
        }
        __syncthreads();
    }

    // epilogue: e = exp(acc*scale); write; per-column partial sums
    float colpart[8];
#pragma unroll
    for (int j = 0; j < 8; j++) colpart[j] = 0.f;
#pragma unroll
    for (int i = 0; i < 8; i++) {
        size_t m = (size_t)(bm0 + ty * 8 + i);
        float* crow = Cp + m * (size_t)NKNOW + bn0 + tx * 8;
        float e[8];
#pragma unroll
        for (int j = 0; j < 8; j++) {
            e[j] = __expf(acc[i][j] * scale);
            colpart[j] += e[j];
        }
        float4 o0 = make_float4(e[0], e[1], e[2], e[3]);
        float4 o1 = make_float4(e[4], e[5], e[6], e[7]);
        *(float4*)(crow)     = o0;
        *(float4*)(crow + 4) = o1;
    }
#pragma unroll
    for (int j = 0; j < 8; j++) red[ty][tx * 8 + j] = colpart[j];
    __syncthreads();
    if (t < 128) {
        float s = 0.f;
#pragma unroll
        for (int r = 0; r < 16; r++) s += red[r][t];
        atomicAdd(&g_colsum[(size_t)z * NKNOW + bn0 + t], s);
    }
}

// ===========================================================================
// Normalize: attn[h][n][m] *= 1/colsum[h][m]  (single read+write pass)
// ===========================================================================
__global__ __launch_bounds__(256)
void normalize_kernel(float* __restrict__ attn)
{
    __shared__ float inv[256];
    const int h = blockIdx.z;
    const int m = blockIdx.x * 256 + threadIdx.x;
    const int n0 = blockIdx.y * 64;
    inv[threadIdx.x] = 1.f / g_colsum[(size_t)h * NKNOW + m];
    float iv = inv[threadIdx.x];
    float* p = attn + (size_t)h * NSENT * NKNOW + (size_t)n0 * NKNOW + m;
#pragma unroll 4
    for (int nn = 0; nn < 64; nn++)
        p[(size_t)nn * NKNOW] *= iv;
}

// ===========================================================================
// tf32 mma.sync GEMM (NN):  fused = attn[h] @ knowledge
//   raw-bit tf32 (HW truncation, no cvt), A-fragments via ldmatrix.x4.b16,
//   3-stage cp.async pipeline. CTA 128x128x32, 8 warps (2x4).
// ===========================================================================
#define MTK 32
#define SA_STRIDE 36
#define SB_STRIDE 136
#define SA_BUF (128 * SA_STRIDE)       // 4608 floats / stage
#define SB_BUF (MTK * SB_STRIDE)       // 4352 floats / stage
#define NSTAGE 3
#define MMA_SMEM (NSTAGE * (SA_BUF + SB_BUF) * 4)   // 107520 bytes

__device__ __forceinline__ void mma_tf32(float* d, const uint32_t* a, const uint32_t* b) {
    asm volatile(
        "mma.sync.aligned.m16n8k8.row.col.f32.tf32.tf32.f32 "
        "{%0,%1,%2,%3}, {%4,%5,%6,%7}, {%8,%9}, {%0,%1,%2,%3};"
        : "+f"(d[0]), "+f"(d[1]), "+f"(d[2]), "+f"(d[3])
        : "r"(a[0]), "r"(a[1]), "r"(a[2]), "r"(a[3]), "r"(b[0]), "r"(b[1]));
}
__device__ __forceinline__ void cp_async16(uint32_t dst, const void* src) {
    asm volatile("cp.async.cg.shared.global [%0], [%1], 16;" :: "r"(dst), "l"(src));
}
__device__ __forceinline__ void ldsm_x4(uint32_t* r, uint32_t addr) {
    asm volatile("ldmatrix.sync.aligned.m8n8.x4.shared.b16 {%0,%1,%2,%3}, [%4];"
                 : "=r"(r[0]), "=r"(r[1]), "=r"(r[2]), "=r"(r[3]) : "r"(addr));
}

__global__ void __launch_bounds__(256, 2)
fused_mma_tf32(const float* __restrict__ A, const float* __restrict__ B,
               float* __restrict__ C)
{
    extern __shared__ float sm[];
    float* sA = sm;                        // NSTAGE x [128][36]
    float* sB = sm + NSTAGE * SA_BUF;      // NSTAGE x [32][136]

    const int tid  = threadIdx.x;
    const int lane = tid & 31;
    const int wid  = tid >> 5;
    const int wm   = wid >> 2;       // 0..1
    const int wn   = wid & 3;        // 0..3
    const int z    = blockIdx.z;
    const int m0   = blockIdx.y * 128;
    const int n0   = blockIdx.x * 128;

    const float* Ap = A + (size_t)z * NSENT * NKNOW + (size_t)m0 * NKNOW;
    const float* Bp = B + n0;

    const int ar  = tid >> 3;                 // A rows ar, +32, +64, +96
    const int ac  = (tid & 7) << 2;           // A k-col
    const int br  = tid >> 5;                 // B k-rows br, +8, +16, +24
    const int bc  = (tid & 31) << 2;          // B n-col

    uint32_t sA_u32 = (uint32_t)__cvta_generic_to_shared(sA);
    uint32_t sB_u32 = (uint32_t)__cvta_generic_to_shared(sB);

    // ldmatrix per-lane offset (bytes): rows lane&15, +4 floats for lanes>=16
    const uint32_t lmoff = (uint32_t)(((lane & 15) * SA_STRIDE + ((lane >> 4) << 2)) * 4);

    float acc[4][4][4];
#pragma unroll
    for (int mt = 0; mt < 4; mt++)
#pragma unroll
        for (int nt = 0; nt < 4; nt++)
#pragma unroll
            for (int r = 0; r < 4; r++) acc[mt][nt][r] = 0.f;

    const int NT = NKNOW / MTK;   // 256

    auto issue = [&](int kt, int s) {
        const float* abase = Ap + (size_t)kt * MTK;
#pragma unroll
        for (int p = 0; p < 4; p++) {
            int row = ar + 32 * p;
            cp_async16(sA_u32 + (uint32_t)(s * SA_BUF + row * SA_STRIDE + ac) * 4,
                       abase + (size_t)row * NKNOW + ac);
        }
        const float* bbase = Bp + (size_t)(kt * MTK) * KFDIM;
#pragma unroll
        for (int p = 0; p < 4; p++) {
            int row = br + 8 * p;
            cp_async16(sB_u32 + (uint32_t)(s * SB_BUF + row * SB_STRIDE + bc) * 4,
                       bbase + (size_t)row * KFDIM + bc);
        }
        asm volatile("cp.async.commit_group;" ::: "memory");
    };

    issue(0, 0);
    issue(1, 1);

    int scur = 0;
    for (int kt = 0; kt < NT; kt++) {
        if (kt + 1 < NT) asm volatile("cp.async.wait_group 1;" ::: "memory");
        else             asm volatile("cp.async.wait_group 0;" ::: "memory");
        __syncthreads();

        if (kt + 2 < NT) {
            int snx = scur + 2; if (snx >= NSTAGE) snx -= NSTAGE;
            issue(kt + 2, snx);
        }

        const uint32_t tA_u32 = sA_u32 + (uint32_t)(scur * SA_BUF) * 4;
        const uint32_t* tBu = (const uint32_t*)(sB + scur * SB_BUF);

#pragma unroll
        for (int ks = 0; ks < 4; ks++) {
            const int kk = ks * 8 + (lane & 3);
            const int nn = wn * 32 + (lane >> 2);
            uint32_t bf[4][2];
#pragma unroll
            for (int nt = 0; nt < 4; nt++) {
                bf[nt][0] = tBu[kk * SB_STRIDE + nn + nt * 8];
                bf[nt][1] = tBu[(kk + 4) * SB_STRIDE + nn + nt * 8];
            }
#pragma unroll
            for (int mt = 0; mt < 4; mt++) {
                uint32_t af[4];
                uint32_t addr = tA_u32 + lmoff +
                    (uint32_t)(((wm * 64 + mt * 16) * SA_STRIDE + ks * 8) * 4);
                ldsm_x4(af, addr);
#pragma unroll
                for (int nt = 0; nt < 4; nt++)
                    mma_tf32(acc[mt][nt], af, bf[nt]);
            }
        }
        scur++; if (scur >= NSTAGE) scur -= NSTAGE;
        __syncthreads();
    }

    const int ldc = NHEADS * KFDIM;
#pragma unroll
    for (int mt = 0; mt < 4; mt++) {
        const int r = m0 + wm * 64 + mt * 16 + (lane >> 2);
#pragma unroll
        for (int nt = 0; nt < 4; nt++) {
            const int c = z * KFDIM + n0 + wn * 32 + nt * 8 + ((lane & 3) << 1);
            float2 v0 = make_float2(acc[mt][nt][0], acc[mt][nt][1]);
            float2 v1 = make_float2(acc[mt][nt][2], acc[mt][nt][3]);
            *(float2*)(C + (size_t)r * ldc + c)        = v0;
            *(float2*)(C + (size_t)(r + 8) * ldc + c)  = v1;
        }
    }
}

// ===========================================================================
// Host side
// ===========================================================================
extern "C" void kernel_launch(void* const* d_in, const int* in_sizes, int n_in,
                              void* d_out, int out_size)
{
    const float* sentences = (const float*)d_in[0];
    const float* knowledge = (const float*)d_in[1];
    const float* w_s       = (const float*)d_in[2];
    const float* b_s       = (const float*)d_in[3];
    const float* w_k       = (const float*)d_in[4];
    const float* b_k       = (const float*)d_in[5];

    float* attn  = (float*)d_out;
    float* fused = (float*)d_out + (size_t)NHEADS * NSENT * NKNOW;

    float *Sbuf = nullptr, *Kbuf = nullptr, *csum = nullptr;
    cudaGetSymbolAddress((void**)&Sbuf, g_S);
    cudaGetSymbolAddress((void**)&Kbuf, g_K);
    cudaGetSymbolAddress((void**)&csum, g_colsum);

    // 0) zero column sums (graph-capturable memset node)
    cudaMemsetAsync(csum, 0, (size_t)NHEADS * NKNOW * sizeof(float));

    // 1) S projection
    {
        dim3 grid(DHEAD / BN, NSENT / BM, NHEADS);
        sgemm_kernel<false, true><<<grid, 256>>>(
            sentences, w_s, b_s, Sbuf,
            NSENT, DHEAD, DMODEL, DMODEL, DHEAD, DHEAD,
            0L, (long)DMODEL * DHEAD, (long)DHEAD, (long)NSENT * DHEAD, 1.0f);
    }
    // 2) K projection
    {
        dim3 grid(DHEAD / BN, NKNOW / BM, NHEADS);
        sgemm_kernel<false, true><<<grid, 256>>>(
            knowledge, w_k, b_k, Kbuf,
            NKNOW, DHEAD, KFDIM, KFDIM, DHEAD, DHEAD,
            0L, (long)KFDIM * DHEAD, (long)DHEAD, (long)NKNOW * DHEAD, 1.0f);
    }
    // 3) scores + exp + colsum
    {
        dim3 grid(NKNOW / BN, NSENT / BM, NHEADS);
        scores_exp_kernel<<<grid, 256>>>(Sbuf, Kbuf, attn, 0.08838834764831845f);
    }
    // 4) normalize (softmax completion)
    {
        dim3 grid(NKNOW / 256, NSENT / 64, NHEADS);
        normalize_kernel<<<grid, 256>>>(attn);
    }
    // 5) fused GEMM on tensor cores (tf32 mma.sync, ldmatrix, 3-stage)
    {
        static bool attr_set = false;
        if (!attr_set) {
            cudaFuncSetAttribute(fused_mma_tf32,
                                 cudaFuncAttributeMaxDynamicSharedMemorySize, MMA_SMEM);
            attr_set = true;
        }
        dim3 grid(KFDIM / 128, NSENT / 128, NHEADS);   // (24, 16, 8)
        fused_mma_tf32<<<grid, 256, MMA_SMEM>>>(attn, knowledge, fused);
    }
}

// round 7
// speedup vs baseline: 3.8633x; 1.2429x over previous
#include <cuda_runtime.h>
#include <cuda_fp16.h>
#include <math.h>
#include <stdint.h>

#define NHEADS 8
#define DMODEL 1024
#define DHEAD  128
#define KFDIM  3072
#define NSENT  2048
#define NKNOW  8192

// Scratch (no cudaMalloc allowed).
__device__ float  g_S[NHEADS * NSENT * DHEAD];     // 8 MB
__device__ float  g_K[NHEADS * NKNOW * DHEAD];     // 32 MB
__device__ float  g_colsum[NHEADS * NKNOW];        // 256 KB
__device__ __half g_Ah[(size_t)NHEADS * NSENT * NKNOW];  // 268 MB: attn fp16 (rna)
__device__ __half g_Bh[(size_t)NKNOW * KFDIM];           // 50 MB: knowledge fp16 (rna)

// ===========================================================================
// fp32 tiled SGEMM (projections)
// ===========================================================================
#define BM 128
#define BN 128
#define BK 8

template<bool TRANS_B, bool HAS_BIAS>
__global__ __launch_bounds__(256)
void sgemm_kernel(const float* __restrict__ A, const float* __restrict__ B,
                  const float* __restrict__ bias, float* __restrict__ C,
                  int M, int N, int K,
                  int lda, int ldb, int ldc,
                  long strideA, long strideB, long strideBias, long strideC,
                  float scale)
{
    __shared__ float As[BK][BM];
    __shared__ float Bs[BK][BN];

    const int t  = threadIdx.x;
    const int z  = blockIdx.z;
    const int bm0 = blockIdx.y * BM;
    const int bn0 = blockIdx.x * BN;

    const float* Ap = A + (size_t)z * strideA;
    const float* Bp = B + (size_t)z * strideB;
    float*       Cp = C + (size_t)z * strideC;

    const int a_row = t >> 1;
    const int a_col = (t & 1) << 2;
    const int b_row = t >> 5;
    const int b_col = (t & 31) << 2;
    const int tb_n  = t >> 1;
    const int tb_k  = (t & 1) << 2;

    const int tx = t & 15;
    const int ty = t >> 4;

    float acc[8][8];
#pragma unroll
    for (int i = 0; i < 8; i++)
#pragma unroll
        for (int j = 0; j < 8; j++) acc[i][j] = 0.f;

    for (int k0 = 0; k0 < K; k0 += BK) {
        float4 av = *(const float4*)(Ap + (size_t)(bm0 + a_row) * lda + k0 + a_col);
        As[a_col + 0][a_row] = av.x;
        As[a_col + 1][a_row] = av.y;
        As[a_col + 2][a_row] = av.z;
        As[a_col + 3][a_row] = av.w;

        if (!TRANS_B) {
            float4 bv = *(const float4*)(Bp + (size_t)(k0 + b_row) * ldb + bn0 + b_col);
            *(float4*)&Bs[b_row][b_col] = bv;
        } else {
            float4 bv = *(const float4*)(Bp + (size_t)(bn0 + tb_n) * ldb + k0 + tb_k);
            Bs[tb_k + 0][tb_n] = bv.x;
            Bs[tb_k + 1][tb_n] = bv.y;
            Bs[tb_k + 2][tb_n] = bv.z;
            Bs[tb_k + 3][tb_n] = bv.w;
        }
        __syncthreads();

#pragma unroll
        for (int kk = 0; kk < BK; kk++) {
            float ar[8], br[8];
            *(float4*)(ar)     = *(const float4*)&As[kk][ty * 8];
            *(float4*)(ar + 4) = *(const float4*)&As[kk][ty * 8 + 4];
            *(float4*)(br)     = *(const float4*)&Bs[kk][tx * 8];
            *(float4*)(br + 4) = *(const float4*)&Bs[kk][tx * 8 + 4];
#pragma unroll
            for (int i = 0; i < 8; i++)
#pragma unroll
                for (int j = 0; j < 8; j++)
                    acc[i][j] = fmaf(ar[i], br[j], acc[i][j]);
        }
        __syncthreads();
    }

    float bv[8];
    if (HAS_BIAS) {
        const float* bp = bias + (size_t)z * strideBias + bn0 + tx * 8;
#pragma unroll
        for (int j = 0; j < 8; j++) bv[j] = bp[j];
    }
#pragma unroll
    for (int i = 0; i < 8; i++) {
        size_t m = (size_t)(bm0 + ty * 8 + i);
        float* crow = Cp + m * (size_t)ldc + bn0 + tx * 8;
        float4 o0, o1;
        o0.x = acc[i][0] * scale; o0.y = acc[i][1] * scale;
        o0.z = acc[i][2] * scale; o0.w = acc[i][3] * scale;
        o1.x = acc[i][4] * scale; o1.y = acc[i][5] * scale;
        o1.z = acc[i][6] * scale; o1.w = acc[i][7] * scale;
        if (HAS_BIAS) {
            o0.x += bv[0]; o0.y += bv[1]; o0.z += bv[2]; o0.w += bv[3];
            o1.x += bv[4]; o1.y += bv[5]; o1.z += bv[6]; o1.w += bv[7];
        }
        *(float4*)(crow)     = o0;
        *(float4*)(crow + 4) = o1;
    }
}

// ===========================================================================
// Scores GEMM (TN, fp32) + fused exp + column partial sums
// ===========================================================================
__global__ __launch_bounds__(256)
void scores_exp_kernel(const float* __restrict__ A, const float* __restrict__ B,
                       float* __restrict__ C, float scale)
{
    __shared__ float As[BK][BM];
    __shared__ float Bs[BK][BN];
    __shared__ float red[16][128];

    const int t  = threadIdx.x;
    const int z  = blockIdx.z;
    const int bm0 = blockIdx.y * BM;
    const int bn0 = blockIdx.x * BN;

    const float* Ap = A + (size_t)z * NSENT * DHEAD;
    const float* Bp = B + (size_t)z * NKNOW * DHEAD;
    float*       Cp = C + (size_t)z * NSENT * NKNOW;

    const int a_row = t >> 1;
    const int a_col = (t & 1) << 2;
    const int tb_n  = t >> 1;
    const int tb_k  = (t & 1) << 2;
    const int tx = t & 15;
    const int ty = t >> 4;

    float acc[8][8];
#pragma unroll
    for (int i = 0; i < 8; i++)
#pragma unroll
        for (int j = 0; j < 8; j++) acc[i][j] = 0.f;

    for (int k0 = 0; k0 < DHEAD; k0 += BK) {
        float4 av = *(const float4*)(Ap + (size_t)(bm0 + a_row) * DHEAD + k0 + a_col);
        As[a_col + 0][a_row] = av.x;
        As[a_col + 1][a_row] = av.y;
        As[a_col + 2][a_row] = av.z;
        As[a_col + 3][a_row] = av.w;
        float4 bv = *(const float4*)(Bp + (size_t)(bn0 + tb_n) * DHEAD + k0 + tb_k);
        Bs[tb_k + 0][tb_n] = bv.x;
        Bs[tb_k + 1][tb_n] = bv.y;
        Bs[tb_k + 2][tb_n] = bv.z;
        Bs[tb_k + 3][tb_n] = bv.w;
        __syncthreads();
#pragma unroll
        for (int kk = 0; kk < BK; kk++) {
            float ar[8], br[8];
            *(float4*)(ar)     = *(const float4*)&As[kk][ty * 8];
            *(float4*)(ar + 4) = *(const float4*)&As[kk][ty * 8 + 4];
            *(float4*)(br)     = *(const float4*)&Bs[kk][tx * 8];
            *(float4*)(br + 4) = *(const float4*)&Bs[kk][tx * 8 + 4];
#pragma unroll
            for (int i = 0; i < 8; i++)
#pragma unroll
                for (int j = 0; j < 8; j++)
                    acc[i][j] = fmaf(ar[i], br[j], acc[i][j]);
        }
        __syncthreads();
    }

    float colpart[8];
#pragma unroll
    for (int j = 0; j < 8; j++) colpart[j] = 0.f;
#pragma unroll
    for (int i = 0; i < 8; i++) {
        size_t m = (size_t)(bm0 + ty * 8 + i);
        float* crow = Cp + m * (size_t)NKNOW + bn0 + tx * 8;
        float e[8];
#pragma unroll
        for (int j = 0; j < 8; j++) {
            e[j] = __expf(acc[i][j] * scale);
            colpart[j] += e[j];
        }
        *(float4*)(crow)     = make_float4(e[0], e[1], e[2], e[3]);
        *(float4*)(crow + 4) = make_float4(e[4], e[5], e[6], e[7]);
    }
#pragma unroll
    for (int j = 0; j < 8; j++) red[ty][tx * 8 + j] = colpart[j];
    __syncthreads();
    if (t < 128) {
        float s = 0.f;
#pragma unroll
        for (int r = 0; r < 16; r++) s += red[r][t];
        atomicAdd(&g_colsum[(size_t)z * NKNOW + bn0 + t], s);
    }
}

// ===========================================================================
// Normalize: attn *= 1/colsum (fp32, exact) + emit rna-fp16 copy for the
// fused tensor-core GEMM.
// ===========================================================================
__global__ __launch_bounds__(256)
void normalize_kernel(float* __restrict__ attn)
{
    const int h = blockIdx.z;
    const int m = blockIdx.x * 256 + threadIdx.x;
    const int n0 = blockIdx.y * 64;
    const float iv = 1.f / g_colsum[(size_t)h * NKNOW + m];
    const size_t base = (size_t)h * NSENT * NKNOW + (size_t)n0 * NKNOW + m;
    float*  p  = attn + base;
    __half* p16 = g_Ah + base;
#pragma unroll 4
    for (int nn = 0; nn < 64; nn++) {
        size_t idx = (size_t)nn * NKNOW;
        float v = p[idx] * iv;
        p[idx]  = v;
        p16[idx] = __float2half_rn(v);
    }
}

// knowledge fp32 -> fp16 (rna)
__global__ __launch_bounds__(256)
void cvt_b16_kernel(const float* __restrict__ in)
{
    size_t i = ((size_t)blockIdx.x * 256 + threadIdx.x) * 4;
    float4 v = *(const float4*)(in + i);
    __half2 h0 = __floats2half2_rn(v.x, v.y);
    __half2 h1 = __floats2half2_rn(v.z, v.w);
    *(__half2*)(g_Bh + i)     = h0;
    *(__half2*)(g_Bh + i + 2) = h1;
}

// ===========================================================================
// fp16 mma.sync GEMM (NN): fused = attn_h16 @ knowledge_h16 (fp32 accum)
//   CTA 128x256x32, 512 threads (16 warps, 4x4, warp tile 32x64),
//   4-stage cp.async, ldmatrix for both operands.
// ===========================================================================
#define FBM 128
#define FBN 256
#define FBK 32
#define FSTG 4
#define SA_STR 40                       // halves per A row (32 + 8 pad)
#define SB_STR 264                      // halves per B row (256 + 8 pad)
#define SA_H (FBM * SA_STR)             // 5120 halves/stage
#define SB_H (FBK * SB_STR)             // 8448 halves/stage
#define FSMEM (FSTG * (SA_H + SB_H) * 2)  // 108544 bytes

__device__ __forceinline__ void mma_f16(float* d, const uint32_t* a, const uint32_t* b) {
    asm volatile(
        "mma.sync.aligned.m16n8k16.row.col.f32.f16.f16.f32 "
        "{%0,%1,%2,%3}, {%4,%5,%6,%7}, {%8,%9}, {%0,%1,%2,%3};"
        : "+f"(d[0]), "+f"(d[1]), "+f"(d[2]), "+f"(d[3])
        : "r"(a[0]), "r"(a[1]), "r"(a[2]), "r"(a[3]), "r"(b[0]), "r"(b[1]));
}
__device__ __forceinline__ void cp_async16(uint32_t dst, const void* src) {
    asm volatile("cp.async.cg.shared.global [%0], [%1], 16;" :: "r"(dst), "l"(src));
}
__device__ __forceinline__ void ldsm_x4(uint32_t* r, uint32_t addr) {
    asm volatile("ldmatrix.sync.aligned.m8n8.x4.shared.b16 {%0,%1,%2,%3}, [%4];"
                 : "=r"(r[0]), "=r"(r[1]), "=r"(r[2]), "=r"(r[3]) : "r"(addr));
}
__device__ __forceinline__ void ldsm_x4_t(uint32_t* r, uint32_t addr) {
    asm volatile("ldmatrix.sync.aligned.m8n8.x4.trans.shared.b16 {%0,%1,%2,%3}, [%4];"
                 : "=r"(r[0]), "=r"(r[1]), "=r"(r[2]), "=r"(r[3]) : "r"(addr));
}

__global__ void __launch_bounds__(512, 1)
fused_mma_f16(float* __restrict__ C)
{
    extern __shared__ __half smh[];
    const uint32_t sA_u32 = (uint32_t)__cvta_generic_to_shared(smh);
    const uint32_t sB_u32 = sA_u32 + FSTG * SA_H * 2;

    const int tid  = threadIdx.x;
    const int lane = tid & 31;
    const int wid  = tid >> 5;
    const int wm   = wid & 3;        // 0..3 (M, 32 rows each)
    const int wn   = wid >> 2;       // 0..3 (N, 64 cols each)
    const int z    = blockIdx.z;
    const int m0   = blockIdx.y * FBM;
    const int n0   = blockIdx.x * FBN;

    const __half* Ap = g_Ah + (size_t)z * NSENT * NKNOW + (size_t)m0 * NKNOW;
    const __half* Bp = g_Bh + n0;

    // A loader: 128 rows x 4 chunks(16B) -> 512 threads, 1 chunk each
    const int a_row = tid >> 2;
    const int a_ch  = (tid & 3) << 3;           // halves
    // B loader: 32 rows x 32 chunks -> 2 chunks/thread
    const int b_row0 = tid >> 5;                // rows 0..15 (t<512: idx t)
    const int b_ch0  = (tid & 31) << 3;

    float acc[2][8][4];
#pragma unroll
    for (int mt = 0; mt < 2; mt++)
#pragma unroll
        for (int nt = 0; nt < 8; nt++)
#pragma unroll
            for (int r = 0; r < 4; r++) acc[mt][nt][r] = 0.f;

    const int NT = NKNOW / FBK;     // 256

    auto issue = [&](int kt, int s) {
        const __half* abase = Ap + (size_t)kt * FBK;
        cp_async16(sA_u32 + (uint32_t)(s * SA_H + a_row * SA_STR + a_ch) * 2,
                   abase + (size_t)a_row * NKNOW + a_ch);
        const __half* bbase = Bp + (size_t)(kt * FBK) * KFDIM;
#pragma unroll
        for (int p = 0; p < 2; p++) {
            int row = b_row0 + p * 16;
            cp_async16(sB_u32 + (uint32_t)(s * SB_H + row * SB_STR + b_ch0) * 2,
                       bbase + (size_t)row * KFDIM + b_ch0);
        }
        asm volatile("cp.async.commit_group;" ::: "memory");
    };

    issue(0, 0);
    issue(1, 1);
    issue(2, 2);

    int scur = 0;
    for (int kt = 0; kt < NT; kt++) {
        if (kt < NT - 2)      asm volatile("cp.async.wait_group 2;" ::: "memory");
        else if (kt == NT - 2) asm volatile("cp.async.wait_group 1;" ::: "memory");
        else                  asm volatile("cp.async.wait_group 0;" ::: "memory");
        __syncthreads();

        if (kt + 3 < NT) {
            int snx = scur + 3; if (snx >= FSTG) snx -= FSTG;
            issue(kt + 3, snx);
        }

        const uint32_t aBase = sA_u32 + (uint32_t)(scur * SA_H) * 2;
        const uint32_t bBase = sB_u32 + (uint32_t)(scur * SB_H) * 2;

#pragma unroll
        for (int ks = 0; ks < 2; ks++) {
            uint32_t bf[8][2];
#pragma unroll
            for (int ntp = 0; ntp < 4; ntp++) {
                uint32_t r[4];
                uint32_t addr = bBase + (uint32_t)(((ks * 16 + (lane & 15)) * SB_STR
                               + wn * 64 + ntp * 16 + ((lane >> 4) << 3)) * 2);
                ldsm_x4_t(r, addr);
                bf[2 * ntp][0]     = r[0];
                bf[2 * ntp][1]     = r[1];
                bf[2 * ntp + 1][0] = r[2];
                bf[2 * ntp + 1][1] = r[3];
            }
#pragma unroll
            for (int mt = 0; mt < 2; mt++) {
                uint32_t af[4];
                uint32_t addr = aBase + (uint32_t)(((wm * 32 + mt * 16 + (lane & 15)) * SA_STR
                               + ks * 16 + ((lane >> 4) << 3)) * 2);
                ldsm_x4(af, addr);
#pragma unroll
                for (int nt = 0; nt < 8; nt++)
                    mma_f16(acc[mt][nt], af, bf[nt]);
            }
        }
        scur++; if (scur >= FSTG) scur -= FSTG;
    }

    const int ldc = NHEADS * KFDIM;
#pragma unroll
    for (int mt = 0; mt < 2; mt++) {
        const int r = m0 + wm * 32 + mt * 16 + (lane >> 2);
#pragma unroll
        for (int nt = 0; nt < 8; nt++) {
            const int c = z * KFDIM + n0 + wn * 64 + nt * 8 + ((lane & 3) << 1);
            *(float2*)(C + (size_t)r * ldc + c)       = make_float2(acc[mt][nt][0], acc[mt][nt][1]);
            *(float2*)(C + (size_t)(r + 8) * ldc + c) = make_float2(acc[mt][nt][2], acc[mt][nt][3]);
        }
    }
}

// ===========================================================================
// Host side
// ===========================================================================
extern "C" void kernel_launch(void* const* d_in, const int* in_sizes, int n_in,
                              void* d_out, int out_size)
{
    const float* sentences = (const float*)d_in[0];
    const float* knowledge = (const float*)d_in[1];
    const float* w_s       = (const float*)d_in[2];
    const float* b_s       = (const float*)d_in[3];
    const float* w_k       = (const float*)d_in[4];
    const float* b_k       = (const float*)d_in[5];

    float* attn  = (float*)d_out;
    float* fused = (float*)d_out + (size_t)NHEADS * NSENT * NKNOW;

    float *Sbuf = nullptr, *Kbuf = nullptr, *csum = nullptr;
    cudaGetSymbolAddress((void**)&Sbuf, g_S);
    cudaGetSymbolAddress((void**)&Kbuf, g_K);
    cudaGetSymbolAddress((void**)&csum, g_colsum);

    // 0) zero column sums; convert knowledge to fp16
    cudaMemsetAsync(csum, 0, (size_t)NHEADS * NKNOW * sizeof(float));
    cvt_b16_kernel<<<(NKNOW * KFDIM) / (256 * 4), 256>>>(knowledge);

    // 1) S projection
    {
        dim3 grid(DHEAD / BN, NSENT / BM, NHEADS);
        sgemm_kernel<false, true><<<grid, 256>>>(
            sentences, w_s, b_s, Sbuf,
            NSENT, DHEAD, DMODEL, DMODEL, DHEAD, DHEAD,
            0L, (long)DMODEL * DHEAD, (long)DHEAD, (long)NSENT * DHEAD, 1.0f);
    }
    // 2) K projection
    {
        dim3 grid(DHEAD / BN, NKNOW / BM, NHEADS);
        sgemm_kernel<false, true><<<grid, 256>>>(
            knowledge, w_k, b_k, Kbuf,
            NKNOW, DHEAD, KFDIM, KFDIM, DHEAD, DHEAD,
            0L, (long)KFDIM * DHEAD, (long)DHEAD, (long)NKNOW * DHEAD, 1.0f);
    }
    // 3) scores + exp + colsum
    {
        dim3 grid(NKNOW / BN, NSENT / BM, NHEADS);
        scores_exp_kernel<<<grid, 256>>>(Sbuf, Kbuf, attn, 0.08838834764831845f);
    }
    // 4) normalize (exact fp32) + fp16 copy for tensor cores
    {
        dim3 grid(NKNOW / 256, NSENT / 64, NHEADS);
        normalize_kernel<<<grid, 256>>>(attn);
    }
    // 5) fused GEMM on fp16 tensor cores
    {
        static bool attr_set = false;
        if (!attr_set) {
            cudaFuncSetAttribute(fused_mma_f16,
                                 cudaFuncAttributeMaxDynamicSharedMemorySize, FSMEM);
            attr_set = true;
        }
        dim3 grid(KFDIM / FBN, NSENT / FBM, NHEADS);   // (12, 16, 8)
        fused_mma_f16<<<grid, 512, FSMEM>>>(fused);
    }
}

// round 8
// speedup vs baseline: 5.6056x; 1.4510x over previous
#include <cuda_runtime.h>
#include <cuda_fp16.h>
#include <math.h>
#include <stdint.h>

#define NHEADS 8
#define DMODEL 1024
#define DHEAD  128
#define KFDIM  3072
#define NSENT  2048
#define NKNOW  8192

// Scratch (no cudaMalloc allowed).
__device__ float  g_S[NHEADS * NSENT * DHEAD];          // 8 MB  (S proj fp32)
__device__ __half g_Sh[NHEADS * NSENT * DHEAD];         // 4 MB  (S fp16)
__device__ __half g_Kh[NHEADS * NKNOW * DHEAD];         // 16 MB (K proj fp16)
__device__ __half g_wkh[NHEADS * KFDIM * DHEAD];        // 6 MB  (w_k fp16)
__device__ float  g_colsum[NHEADS * NKNOW];             // 256 KB
__device__ __half g_Ah[(size_t)NHEADS * NSENT * NKNOW]; // 268 MB (attn fp16)
__device__ __half g_Bh[(size_t)NKNOW * KFDIM];          // 50 MB (knowledge fp16)

// ===========================================================================
// mma/ldmatrix/cp.async helpers
// ===========================================================================
__device__ __forceinline__ void mma_f16(float* d, const uint32_t* a, const uint32_t* b) {
    asm volatile(
        "mma.sync.aligned.m16n8k16.row.col.f32.f16.f16.f32 "
        "{%0,%1,%2,%3}, {%4,%5,%6,%7}, {%8,%9}, {%0,%1,%2,%3};"
        : "+f"(d[0]), "+f"(d[1]), "+f"(d[2]), "+f"(d[3])
        : "r"(a[0]), "r"(a[1]), "r"(a[2]), "r"(a[3]), "r"(b[0]), "r"(b[1]));
}
__device__ __forceinline__ void cp_async16(uint32_t dst, const void* src) {
    asm volatile("cp.async.cg.shared.global [%0], [%1], 16;" :: "r"(dst), "l"(src));
}
__device__ __forceinline__ void ldsm_x4(uint32_t* r, uint32_t addr) {
    asm volatile("ldmatrix.sync.aligned.m8n8.x4.shared.b16 {%0,%1,%2,%3}, [%4];"
                 : "=r"(r[0]), "=r"(r[1]), "=r"(r[2]), "=r"(r[3]) : "r"(addr));
}
__device__ __forceinline__ void ldsm_x4_t(uint32_t* r, uint32_t addr) {
    asm volatile("ldmatrix.sync.aligned.m8n8.x4.trans.shared.b16 {%0,%1,%2,%3}, [%4];"
                 : "=r"(r[0]), "=r"(r[1]), "=r"(r[2]), "=r"(r[3]) : "r"(addr));
}

// ===========================================================================
// fp32 tiled SGEMM (S projection only)
// ===========================================================================
#define BM 128
#define BN 128
#define BK 8

template<bool TRANS_B, bool HAS_BIAS>
__global__ __launch_bounds__(256)
void sgemm_kernel(const float* __restrict__ A, const float* __restrict__ B,
                  const float* __restrict__ bias, float* __restrict__ C,
                  int M, int N, int K,
                  int lda, int ldb, int ldc,
                  long strideA, long strideB, long strideBias, long strideC,
                  float scale)
{
    __shared__ float As[BK][BM];
    __shared__ float Bs[BK][BN];

    const int t  = threadIdx.x;
    const int z  = blockIdx.z;
    const int bm0 = blockIdx.y * BM;
    const int bn0 = blockIdx.x * BN;

    const float* Ap = A + (size_t)z * strideA;
    const float* Bp = B + (size_t)z * strideB;
    float*       Cp = C + (size_t)z * strideC;

    const int a_row = t >> 1;
    const int a_col = (t & 1) << 2;
    const int b_row = t >> 5;
    const int b_col = (t & 31) << 2;
    const int tb_n  = t >> 1;
    const int tb_k  = (t & 1) << 2;

    const int tx = t & 15;
    const int ty = t >> 4;

    float acc[8][8];
#pragma unroll
    for (int i = 0; i < 8; i++)
#pragma unroll
        for (int j = 0; j < 8; j++) acc[i][j] = 0.f;

    for (int k0 = 0; k0 < K; k0 += BK) {
        float4 av = *(const float4*)(Ap + (size_t)(bm0 + a_row) * lda + k0 + a_col);
        As[a_col + 0][a_row] = av.x;
        As[a_col + 1][a_row] = av.y;
        As[a_col + 2][a_row] = av.z;
        As[a_col + 3][a_row] = av.w;

        if (!TRANS_B) {
            float4 bv = *(const float4*)(Bp + (size_t)(k0 + b_row) * ldb + bn0 + b_col);
            *(float4*)&Bs[b_row][b_col] = bv;
        } else {
            float4 bv = *(const float4*)(Bp + (size_t)(bn0 + tb_n) * ldb + k0 + tb_k);
            Bs[tb_k + 0][tb_n] = bv.x;
            Bs[tb_k + 1][tb_n] = bv.y;
            Bs[tb_k + 2][tb_n] = bv.z;
            Bs[tb_k + 3][tb_n] = bv.w;
        }
        __syncthreads();

#pragma unroll
        for (int kk = 0; kk < BK; kk++) {
            float ar[8], br[8];
            *(float4*)(ar)     = *(const float4*)&As[kk][ty * 8];
            *(float4*)(ar + 4) = *(const float4*)&As[kk][ty * 8 + 4];
            *(float4*)(br)     = *(const float4*)&Bs[kk][tx * 8];
            *(float4*)(br + 4) = *(const float4*)&Bs[kk][tx * 8 + 4];
#pragma unroll
            for (int i = 0; i < 8; i++)
#pragma unroll
                for (int j = 0; j < 8; j++)
                    acc[i][j] = fmaf(ar[i], br[j], acc[i][j]);
        }
        __syncthreads();
    }

    float bv[8];
    if (HAS_BIAS) {
        const float* bp = bias + (size_t)z * strideBias + bn0 + tx * 8;
#pragma unroll
        for (int j = 0; j < 8; j++) bv[j] = bp[j];
    }
#pragma unroll
    for (int i = 0; i < 8; i++) {
        size_t m = (size_t)(bm0 + ty * 8 + i);
        float* crow = Cp + m * (size_t)ldc + bn0 + tx * 8;
        float4 o0, o1;
        o0.x = acc[i][0] * scale; o0.y = acc[i][1] * scale;
        o0.z = acc[i][2] * scale; o0.w = acc[i][3] * scale;
        o1.x = acc[i][4] * scale; o1.y = acc[i][5] * scale;
        o1.z = acc[i][6] * scale; o1.w = acc[i][7] * scale;
        if (HAS_BIAS) {
            o0.x += bv[0]; o0.y += bv[1]; o0.z += bv[2]; o0.w += bv[3];
            o1.x += bv[4]; o1.y += bv[5]; o1.z += bv[6]; o1.w += bv[7];
        }
        *(float4*)(crow)     = o0;
        *(float4*)(crow + 4) = o1;
    }
}

// ===========================================================================
// fp32 -> fp16 (rn) converter
// ===========================================================================
__global__ __launch_bounds__(256)
void cvt_f16_kernel(const float* __restrict__ in, __half* __restrict__ out)
{
    size_t i = ((size_t)blockIdx.x * 256 + threadIdx.x) * 4;
    float4 v = *(const float4*)(in + i);
    *(__half2*)(out + i)     = __floats2half2_rn(v.x, v.y);
    *(__half2*)(out + i + 2) = __floats2half2_rn(v.z, v.w);
}

// ===========================================================================
// K projection on fp16 tensor cores:
//   g_Kh[z][m][n] = f16( g_Bh[m,:] @ g_wkh[z][:,n] + b_k[z][n] )
//   A: [NKNOW, KFDIM] fp16 row-major (NN);  B: [KFDIM, DHEAD] fp16 row-major
//   CTA 128x128xK32, 256 thr (8 warps 2x4, warp 64x32), 4-stage cp.async
// ===========================================================================
#define KP_STG 4
#define KPA_STR 40
#define KPB_STR 136
#define KPA_H (128 * KPA_STR)   // 5120 halves/stage
#define KPB_H (32 * KPB_STR)    // 4352 halves/stage
#define KPSMEM (KP_STG * (KPA_H + KPB_H) * 2)   // 75776 B

__global__ void __launch_bounds__(256, 2)
kproj_f16_kernel(const float* __restrict__ bias)
{
    extern __shared__ __half kps[];
    const uint32_t sA = (uint32_t)__cvta_generic_to_shared(kps);
    const uint32_t sB = sA + KP_STG * KPA_H * 2;

    const int tid  = threadIdx.x;
    const int lane = tid & 31;
    const int wid  = tid >> 5;
    const int wm   = wid >> 2;       // 0..1
    const int wn   = wid & 3;        // 0..3
    const int z    = blockIdx.z;
    const int m0   = blockIdx.y * 128;

    const __half* Ap = g_Bh + (size_t)m0 * KFDIM;
    const __half* Bp = g_wkh + (size_t)z * KFDIM * DHEAD;

    const int a_r = tid >> 1;               // 0..127
    const int a_c = (tid & 1) << 4;         // 0 or 16 halves
    const int b_r = tid >> 3;               // 0..31
    const int b_c = (tid & 7) << 4;         // 0..112 halves

    float acc[4][4][4];
#pragma unroll
    for (int mt = 0; mt < 4; mt++)
#pragma unroll
        for (int nt = 0; nt < 4; nt++)
#pragma unroll
            for (int r = 0; r < 4; r++) acc[mt][nt][r] = 0.f;

    const int NT = KFDIM / 32;   // 96

    auto issue = [&](int kt, int s) {
#pragma unroll
        for (int i = 0; i < 2; i++)
            cp_async16(sA + (uint32_t)(s * KPA_H + a_r * KPA_STR + a_c + 8 * i) * 2,
                       Ap + (size_t)a_r * KFDIM + kt * 32 + a_c + 8 * i);
#pragma unroll
        for (int i = 0; i < 2; i++)
            cp_async16(sB + (uint32_t)(s * KPB_H + b_r * KPB_STR + b_c + 8 * i) * 2,
                       Bp + (size_t)(kt * 32 + b_r) * DHEAD + b_c + 8 * i);
        asm volatile("cp.async.commit_group;" ::: "memory");
    };

    issue(0, 0); issue(1, 1); issue(2, 2);

    int scur = 0;
    for (int kt = 0; kt < NT; kt++) {
        if (kt < NT - 2)       asm volatile("cp.async.wait_group 2;" ::: "memory");
        else if (kt == NT - 2) asm volatile("cp.async.wait_group 1;" ::: "memory");
        else                   asm volatile("cp.async.wait_group 0;" ::: "memory");
        __syncthreads();

        if (kt + 3 < NT) {
            int snx = scur + 3; if (snx >= KP_STG) snx -= KP_STG;
            issue(kt + 3, snx);
        }

        const uint32_t aB = sA + (uint32_t)(scur * KPA_H) * 2;
        const uint32_t bB = sB + (uint32_t)(scur * KPB_H) * 2;

#pragma unroll
        for (int ks = 0; ks < 2; ks++) {
            uint32_t bf[4][2];
#pragma unroll
            for (int ntp = 0; ntp < 2; ntp++) {
                uint32_t r[4];
                uint32_t addr = bB + (uint32_t)(((ks * 16 + (lane & 15)) * KPB_STR
                               + wn * 32 + ntp * 16 + ((lane >> 4) << 3)) * 2);
                ldsm_x4_t(r, addr);
                bf[2 * ntp][0]     = r[0];
                bf[2 * ntp][1]     = r[1];
                bf[2 * ntp + 1][0] = r[2];
                bf[2 * ntp + 1][1] = r[3];
            }
#pragma unroll
            for (int mt = 0; mt < 4; mt++) {
                uint32_t af[4];
                uint32_t addr = aB + (uint32_t)(((wm * 64 + mt * 16 + (lane & 15)) * KPA_STR
                               + ks * 16 + ((lane >> 4) << 3)) * 2);
                ldsm_x4(af, addr);
#pragma unroll
                for (int nt = 0; nt < 4; nt++)
                    mma_f16(acc[mt][nt], af, bf[nt]);
            }
        }
        scur++; if (scur >= KP_STG) scur -= KP_STG;
        __syncthreads();
    }

    // epilogue: + bias, fp16 store
    __half* Kp = g_Kh + (size_t)z * NKNOW * DHEAD;
#pragma unroll
    for (int mt = 0; mt < 4; mt++) {
        const int r = m0 + wm * 64 + mt * 16 + (lane >> 2);
#pragma unroll
        for (int nt = 0; nt < 4; nt++) {
            const int c = wn * 32 + nt * 8 + ((lane & 3) << 1);
            float b0 = bias[z * DHEAD + c], b1 = bias[z * DHEAD + c + 1];
            *(__half2*)(Kp + (size_t)r * DHEAD + c) =
                __floats2half2_rn(acc[mt][nt][0] + b0, acc[mt][nt][1] + b1);
            *(__half2*)(Kp + (size_t)(r + 8) * DHEAD + c) =
                __floats2half2_rn(acc[mt][nt][2] + b0, acc[mt][nt][3] + b1);
        }
    }
}

// ===========================================================================
// Scores on fp16 tensor cores (NT) + fp32 exp + column partial sums.
//   attn[z][m][n] = exp(scale * Sh[z][m,:] . Kh[z][n,:]),  colsum += partials
//   K=128 one-shot smem. CTA 128x128, 256 thr (8 warps 2x4, warp 64x32).
// ===========================================================================
#define SC_STR 136
#define SC_SMEM (2 * 128 * SC_STR * 2)   // 69632 B dynamic

__global__ void __launch_bounds__(256, 2)
scores_f16_kernel(float* __restrict__ attn, float scale)
{
    extern __shared__ __half scs[];
    const uint32_t sA = (uint32_t)__cvta_generic_to_shared(scs);
    const uint32_t sB = sA + 128 * SC_STR * 2;
    __shared__ float red[16][128];

    const int tid  = threadIdx.x;
    const int lane = tid & 31;
    const int wid  = tid >> 5;
    const int wm   = wid >> 2;
    const int wn   = wid & 3;
    const int z    = blockIdx.z;
    const int m0   = blockIdx.y * 128;
    const int n0   = blockIdx.x * 128;

    const __half* Ap = g_Sh + (size_t)z * NSENT * DHEAD + (size_t)m0 * DHEAD;
    const __half* Bp = g_Kh + (size_t)z * NKNOW * DHEAD + (size_t)n0 * DHEAD;

    // one-shot load: 8 chunks each of A and B per thread
    {
        const int r  = tid >> 1;
        const int c0 = (tid & 1) << 6;       // 0 or 64 halves
#pragma unroll
        for (int i = 0; i < 8; i++) {
            cp_async16(sA + (uint32_t)(r * SC_STR + c0 + 8 * i) * 2,
                       Ap + (size_t)r * DHEAD + c0 + 8 * i);
            cp_async16(sB + (uint32_t)(r * SC_STR + c0 + 8 * i) * 2,
                       Bp + (size_t)r * DHEAD + c0 + 8 * i);
        }
        asm volatile("cp.async.commit_group;" ::: "memory");
        asm volatile("cp.async.wait_group 0;" ::: "memory");
        __syncthreads();
    }

    float acc[4][4][4];
#pragma unroll
    for (int mt = 0; mt < 4; mt++)
#pragma unroll
        for (int nt = 0; nt < 4; nt++)
#pragma unroll
            for (int r = 0; r < 4; r++) acc[mt][nt][r] = 0.f;

#pragma unroll
    for (int ks = 0; ks < 8; ks++) {
        uint32_t bf[4][2];
#pragma unroll
        for (int ntp = 0; ntp < 2; ntp++) {
            uint32_t r[4];
            uint32_t addr = sB + (uint32_t)(((wn * 32 + ntp * 16 + (lane & 15)) * SC_STR
                           + ks * 16 + ((lane >> 4) << 3)) * 2);
            ldsm_x4(r, addr);      // rows = n, cols = k  (NT B fragment)
            bf[2 * ntp][0]     = r[0];
            bf[2 * ntp][1]     = r[2];
            bf[2 * ntp + 1][0] = r[1];
            bf[2 * ntp + 1][1] = r[3];
        }
#pragma unroll
        for (int mt = 0; mt < 4; mt++) {
            uint32_t af[4];
            uint32_t addr = sA + (uint32_t)(((wm * 64 + mt * 16 + (lane & 15)) * SC_STR
                           + ks * 16 + ((lane >> 4) << 3)) * 2);
            ldsm_x4(af, addr);
#pragma unroll
            for (int nt = 0; nt < 4; nt++)
                mma_f16(acc[mt][nt], af, bf[nt]);
        }
    }

    // epilogue: exp (fp32), write attn, column partial sums
    float cp[8];
#pragma unroll
    for (int j = 0; j < 8; j++) cp[j] = 0.f;
    float* Cp = attn + (size_t)z * NSENT * NKNOW;
#pragma unroll
    for (int mt = 0; mt < 4; mt++) {
        const int r = m0 + wm * 64 + mt * 16 + (lane >> 2);
#pragma unroll
        for (int nt = 0; nt < 4; nt++) {
            const int c = n0 + wn * 32 + nt * 8 + ((lane & 3) << 1);
            float e0 = __expf(acc[mt][nt][0] * scale);
            float e1 = __expf(acc[mt][nt][1] * scale);
            float e2 = __expf(acc[mt][nt][2] * scale);
            float e3 = __expf(acc[mt][nt][3] * scale);
            *(float2*)(Cp + (size_t)r * NKNOW + c)       = make_float2(e0, e1);
            *(float2*)(Cp + (size_t)(r + 8) * NKNOW + c) = make_float2(e2, e3);
            cp[nt * 2]     += e0 + e2;
            cp[nt * 2 + 1] += e1 + e3;
        }
    }
    const int rr = wm * 8 + (lane >> 2);
#pragma unroll
    for (int nt = 0; nt < 4; nt++) {
        red[rr][wn * 32 + nt * 8 + ((lane & 3) << 1)]     = cp[nt * 2];
        red[rr][wn * 32 + nt * 8 + ((lane & 3) << 1) + 1] = cp[nt * 2 + 1];
    }
    __syncthreads();
    if (tid < 128) {
        float s = 0.f;
#pragma unroll
        for (int r = 0; r < 16; r++) s += red[r][tid];
        atomicAdd(&g_colsum[(size_t)z * NKNOW + n0 + tid], s);
    }
}

// ===========================================================================
// Normalize: attn *= 1/colsum (fp32 exact) + rna-fp16 copy for fused GEMM
// ===========================================================================
__global__ __launch_bounds__(256)
void normalize_kernel(float* __restrict__ attn)
{
    const int h = blockIdx.z;
    const int m = blockIdx.x * 256 + threadIdx.x;
    const int n0 = blockIdx.y * 64;
    const float iv = 1.f / g_colsum[(size_t)h * NKNOW + m];
    const size_t base = (size_t)h * NSENT * NKNOW + (size_t)n0 * NKNOW + m;
    float*  p   = attn + base;
    __half* p16 = g_Ah + base;
#pragma unroll 4
    for (int nn = 0; nn < 64; nn++) {
        size_t idx = (size_t)nn * NKNOW;
        float v = p[idx] * iv;
        p[idx]   = v;
        p16[idx] = __float2half_rn(v);
    }
}

// ===========================================================================
// fused = attn_h16 @ knowledge_h16 (fp16 mma, fp32 accum)
//   CTA 128x256x32, 512 thr (16 warps 4x4, warp 32x64), 4-stage cp.async
// ===========================================================================
#define FBM 128
#define FBN 256
#define FBK 32
#define FSTG 4
#define SA_STR 40
#define SB_STR 264
#define SA_H (FBM * SA_STR)
#define SB_H (FBK * SB_STR)
#define FSMEM (FSTG * (SA_H + SB_H) * 2)

__global__ void __launch_bounds__(512, 1)
fused_mma_f16(float* __restrict__ C)
{
    extern __shared__ __half smh[];
    const uint32_t sA_u32 = (uint32_t)__cvta_generic_to_shared(smh);
    const uint32_t sB_u32 = sA_u32 + FSTG * SA_H * 2;

    const int tid  = threadIdx.x;
    const int lane = tid & 31;
    const int wid  = tid >> 5;
    const int wm   = wid & 3;
    const int wn   = wid >> 2;
    const int z    = blockIdx.z;
    const int m0   = blockIdx.y * FBM;
    const int n0   = blockIdx.x * FBN;

    const __half* Ap = g_Ah + (size_t)z * NSENT * NKNOW + (size_t)m0 * NKNOW;
    const __half* Bp = g_Bh + n0;

    const int a_row = tid >> 2;
    const int a_ch  = (tid & 3) << 3;
    const int b_row0 = tid >> 5;
    const int b_ch0  = (tid & 31) << 3;

    float acc[2][8][4];
#pragma unroll
    for (int mt = 0; mt < 2; mt++)
#pragma unroll
        for (int nt = 0; nt < 8; nt++)
#pragma unroll
            for (int r = 0; r < 4; r++) acc[mt][nt][r] = 0.f;

    const int NT = NKNOW / FBK;

    auto issue = [&](int kt, int s) {
        const __half* abase = Ap + (size_t)kt * FBK;
        cp_async16(sA_u32 + (uint32_t)(s * SA_H + a_row * SA_STR + a_ch) * 2,
                   abase + (size_t)a_row * NKNOW + a_ch);
        const __half* bbase = Bp + (size_t)(kt * FBK) * KFDIM;
#pragma unroll
        for (int p = 0; p < 2; p++) {
            int row = b_row0 + p * 16;
            cp_async16(sB_u32 + (uint32_t)(s * SB_H + row * SB_STR + b_ch0) * 2,
                       bbase + (size_t)row * KFDIM + b_ch0);
        }
        asm volatile("cp.async.commit_group;" ::: "memory");
    };

    issue(0, 0); issue(1, 1); issue(2, 2);

    int scur = 0;
    for (int kt = 0; kt < NT; kt++) {
        if (kt < NT - 2)       asm volatile("cp.async.wait_group 2;" ::: "memory");
        else if (kt == NT - 2) asm volatile("cp.async.wait_group 1;" ::: "memory");
        else                   asm volatile("cp.async.wait_group 0;" ::: "memory");
        __syncthreads();

        if (kt + 3 < NT) {
            int snx = scur + 3; if (snx >= FSTG) snx -= FSTG;
            issue(kt + 3, snx);
        }

        const uint32_t aBase = sA_u32 + (uint32_t)(scur * SA_H) * 2;
        const uint32_t bBase = sB_u32 + (uint32_t)(scur * SB_H) * 2;

#pragma unroll
        for (int ks = 0; ks < 2; ks++) {
            uint32_t bf[8][2];
#pragma unroll
            for (int ntp = 0; ntp < 4; ntp++) {
                uint32_t r[4];
                uint32_t addr = bBase + (uint32_t)(((ks * 16 + (lane & 15)) * SB_STR
                               + wn * 64 + ntp * 16 + ((lane >> 4) << 3)) * 2);
                ldsm_x4_t(r, addr);
                bf[2 * ntp][0]     = r[0];
                bf[2 * ntp][1]     = r[1];
                bf[2 * ntp + 1][0] = r[2];
                bf[2 * ntp + 1][1] = r[3];
            }
#pragma unroll
            for (int mt = 0; mt < 2; mt++) {
                uint32_t af[4];
                uint32_t addr = aBase + (uint32_t)(((wm * 32 + mt * 16 + (lane & 15)) * SA_STR
                               + ks * 16 + ((lane >> 4) << 3)) * 2);
                ldsm_x4(af, addr);
#pragma unroll
                for (int nt = 0; nt < 8; nt++)
                    mma_f16(acc[mt][nt], af, bf[nt]);
            }
        }
        scur++; if (scur >= FSTG) scur -= FSTG;
    }

    const int ldc = NHEADS * KFDIM;
#pragma unroll
    for (int mt = 0; mt < 2; mt++) {
        const int r = m0 + wm * 32 + mt * 16 + (lane >> 2);
#pragma unroll
        for (int nt = 0; nt < 8; nt++) {
            const int c = z * KFDIM + n0 + wn * 64 + nt * 8 + ((lane & 3) << 1);
            *(float2*)(C + (size_t)r * ldc + c)       = make_float2(acc[mt][nt][0], acc[mt][nt][1]);
            *(float2*)(C + (size_t)(r + 8) * ldc + c) = make_float2(acc[mt][nt][2], acc[mt][nt][3]);
        }
    }
}

// ===========================================================================
// Host side
// ===========================================================================
extern "C" void kernel_launch(void* const* d_in, const int* in_sizes, int n_in,
                              void* d_out, int out_size)
{
    const float* sentences = (const float*)d_in[0];
    const float* knowledge = (const float*)d_in[1];
    const float* w_s       = (const float*)d_in[2];
    const float* b_s       = (const float*)d_in[3];
    const float* w_k       = (const float*)d_in[4];
    const float* b_k       = (const float*)d_in[5];

    float* attn  = (float*)d_out;
    float* fused = (float*)d_out + (size_t)NHEADS * NSENT * NKNOW;

    float *Sbuf = nullptr, *csum = nullptr;
    __half *Sh = nullptr, *Bh = nullptr, *wkh = nullptr;
    cudaGetSymbolAddress((void**)&Sbuf, g_S);
    cudaGetSymbolAddress((void**)&csum, g_colsum);
    cudaGetSymbolAddress((void**)&Sh,  g_Sh);
    cudaGetSymbolAddress((void**)&Bh,  g_Bh);
    cudaGetSymbolAddress((void**)&wkh, g_wkh);

    // 0) zero colsums; fp16 conversions of knowledge and w_k
    cudaMemsetAsync(csum, 0, (size_t)NHEADS * NKNOW * sizeof(float));
    cvt_f16_kernel<<<((size_t)NKNOW * KFDIM) / (256 * 4), 256>>>(knowledge, Bh);
    cvt_f16_kernel<<<((size_t)NHEADS * KFDIM * DHEAD) / (256 * 4), 256>>>(w_k, wkh);

    // 1) S projection (fp32) + fp16 copy
    {
        dim3 grid(DHEAD / BN, NSENT / BM, NHEADS);
        sgemm_kernel<false, true><<<grid, 256>>>(
            sentences, w_s, b_s, Sbuf,
            NSENT, DHEAD, DMODEL, DMODEL, DHEAD, DHEAD,
            0L, (long)DMODEL * DHEAD, (long)DHEAD, (long)NSENT * DHEAD, 1.0f);
        cvt_f16_kernel<<<((size_t)NHEADS * NSENT * DHEAD) / (256 * 4), 256>>>(Sbuf, Sh);
    }
    // 2) K projection on fp16 tensor cores
    {
        static bool a1 = false;
        if (!a1) { cudaFuncSetAttribute(kproj_f16_kernel,
                     cudaFuncAttributeMaxDynamicSharedMemorySize, KPSMEM); a1 = true; }
        dim3 grid(1, NKNOW / 128, NHEADS);
        kproj_f16_kernel<<<grid, 256, KPSMEM>>>(b_k);
    }
    // 3) scores (fp16 mma) + exp + colsum
    {
        static bool a2 = false;
        if (!a2) { cudaFuncSetAttribute(scores_f16_kernel,
                     cudaFuncAttributeMaxDynamicSharedMemorySize, SC_SMEM); a2 = true; }
        dim3 grid(NKNOW / 128, NSENT / 128, NHEADS);
        scores_f16_kernel<<<grid, 256, SC_SMEM>>>(attn, 0.08838834764831845f);
    }
    // 4) normalize + fp16 attn copy
    {
        dim3 grid(NKNOW / 256, NSENT / 64, NHEADS);
        normalize_kernel<<<grid, 256>>>(attn);
    }
    // 5) fused GEMM on fp16 tensor cores
    {
        static bool a3 = false;
        if (!a3) { cudaFuncSetAttribute(fused_mma_f16,
                     cudaFuncAttributeMaxDynamicSharedMemorySize, FSMEM); a3 = true; }
        dim3 grid(KFDIM / FBN, NSENT / FBM, NHEADS);
        fused_mma_f16<<<grid, 512, FSMEM>>>(fused);
    }
}

// round 9
// speedup vs baseline: 6.5626x; 1.1707x over previous
#include <cuda_runtime.h>
#include <cuda_fp16.h>
#include <math.h>
#include <stdint.h>

#define NHEADS 8
#define DMODEL 1024
#define DHEAD  128
#define KFDIM  3072
#define NSENT  2048
#define NKNOW  8192

// Scratch (no cudaMalloc allowed).
__device__ __half g_snth[NSENT * DMODEL];               // 4 MB  sentences fp16
__device__ __half g_wsh[NHEADS * DMODEL * DHEAD];       // 2 MB  w_s fp16
__device__ __half g_Sh[NHEADS * NSENT * DHEAD];         // 4 MB  S fp16
__device__ __half g_Kh[NHEADS * NKNOW * DHEAD];         // 16 MB K fp16
__device__ __half g_wkh[NHEADS * KFDIM * DHEAD];        // 6 MB  w_k fp16
__device__ float  g_colsum[NHEADS * NKNOW];             // 256 KB
__device__ __half g_Ah[(size_t)NHEADS * NSENT * NKNOW]; // 268 MB exp/attn fp16
__device__ __half g_Bh[(size_t)NKNOW * KFDIM];          // 50 MB knowledge fp16

// ===========================================================================
// helpers
// ===========================================================================
__device__ __forceinline__ void mma_f16(float* d, const uint32_t* a, const uint32_t* b) {
    asm volatile(
        "mma.sync.aligned.m16n8k16.row.col.f32.f16.f16.f32 "
        "{%0,%1,%2,%3}, {%4,%5,%6,%7}, {%8,%9}, {%0,%1,%2,%3};"
        : "+f"(d[0]), "+f"(d[1]), "+f"(d[2]), "+f"(d[3])
        : "r"(a[0]), "r"(a[1]), "r"(a[2]), "r"(a[3]), "r"(b[0]), "r"(b[1]));
}
__device__ __forceinline__ void cp_async16(uint32_t dst, const void* src) {
    asm volatile("cp.async.cg.shared.global [%0], [%1], 16;" :: "r"(dst), "l"(src));
}
__device__ __forceinline__ void ldsm_x4(uint32_t* r, uint32_t addr) {
    asm volatile("ldmatrix.sync.aligned.m8n8.x4.shared.b16 {%0,%1,%2,%3}, [%4];"
                 : "=r"(r[0]), "=r"(r[1]), "=r"(r[2]), "=r"(r[3]) : "r"(addr));
}
__device__ __forceinline__ void ldsm_x4_t(uint32_t* r, uint32_t addr) {
    asm volatile("ldmatrix.sync.aligned.m8n8.x4.trans.shared.b16 {%0,%1,%2,%3}, [%4];"
                 : "=r"(r[0]), "=r"(r[1]), "=r"(r[2]), "=r"(r[3]) : "r"(addr));
}

// fp32 -> fp16 (rn)
__global__ __launch_bounds__(256)
void cvt_f16_kernel(const float* __restrict__ in, __half* __restrict__ out)
{
    size_t i = ((size_t)blockIdx.x * 256 + threadIdx.x) * 4;
    float4 v = *(const float4*)(in + i);
    *(__half2*)(out + i)     = __floats2half2_rn(v.x, v.y);
    *(__half2*)(out + i + 2) = __floats2half2_rn(v.z, v.w);
}

// ===========================================================================
// Generic per-head projection on fp16 tensor cores:
//   out[z][m][n] = f16( A[m,:] @ W[z][:,n] + bias[z][n] ),  n < 128
//   A: [Mtot, Kdim] fp16 row-major (shared across heads)
//   W: [Kdim, DHEAD] fp16 row-major per head
//   CTA 128x128xK32, 256 thr (8 warps 2x4, warp 64x32), 4-stage cp.async
// ===========================================================================
#define KP_STG 4
#define KPA_STR 40
#define KPB_STR 136
#define KPA_H (128 * KPA_STR)
#define KPB_H (32 * KPB_STR)
#define KPSMEM (KP_STG * (KPA_H + KPB_H) * 2)   // 75776 B

__global__ void __launch_bounds__(256, 2)
proj_f16_kernel(const __half* __restrict__ A, const __half* __restrict__ W,
                const float* __restrict__ bias, __half* __restrict__ out,
                int Kdim, int Mtot)
{
    extern __shared__ __half kps[];
    const uint32_t sA = (uint32_t)__cvta_generic_to_shared(kps);
    const uint32_t sB = sA + KP_STG * KPA_H * 2;

    const int tid  = threadIdx.x;
    const int lane = tid & 31;
    const int wid  = tid >> 5;
    const int wm   = wid >> 2;
    const int wn   = wid & 3;
    const int z    = blockIdx.z;
    const int m0   = blockIdx.y * 128;

    const __half* Ap = A + (size_t)m0 * Kdim;
    const __half* Bp = W + (size_t)z * Kdim * DHEAD;

    const int a_r = tid >> 1;
    const int a_c = (tid & 1) << 4;
    const int b_r = tid >> 3;
    const int b_c = (tid & 7) << 4;

    float acc[4][4][4];
#pragma unroll
    for (int mt = 0; mt < 4; mt++)
#pragma unroll
        for (int nt = 0; nt < 4; nt++)
#pragma unroll
            for (int r = 0; r < 4; r++) acc[mt][nt][r] = 0.f;

    const int NT = Kdim / 32;

    auto issue = [&](int kt, int s) {
#pragma unroll
        for (int i = 0; i < 2; i++)
            cp_async16(sA + (uint32_t)(s * KPA_H + a_r * KPA_STR + a_c + 8 * i) * 2,
                       Ap + (size_t)a_r * Kdim + kt * 32 + a_c + 8 * i);
#pragma unroll
        for (int i = 0; i < 2; i++)
            cp_async16(sB + (uint32_t)(s * KPB_H + b_r * KPB_STR + b_c + 8 * i) * 2,
                       Bp + (size_t)(kt * 32 + b_r) * DHEAD + b_c + 8 * i);
        asm volatile("cp.async.commit_group;" ::: "memory");
    };

    issue(0, 0); issue(1, 1); issue(2, 2);

    int scur = 0;
    for (int kt = 0; kt < NT; kt++) {
        if (kt < NT - 2)       asm volatile("cp.async.wait_group 2;" ::: "memory");
        else if (kt == NT - 2) asm volatile("cp.async.wait_group 1;" ::: "memory");
        else                   asm volatile("cp.async.wait_group 0;" ::: "memory");
        __syncthreads();

        if (kt + 3 < NT) {
            int snx = scur + 3; if (snx >= KP_STG) snx -= KP_STG;
            issue(kt + 3, snx);
        }

        const uint32_t aB = sA + (uint32_t)(scur * KPA_H) * 2;
        const uint32_t bB = sB + (uint32_t)(scur * KPB_H) * 2;

#pragma unroll
        for (int ks = 0; ks < 2; ks++) {
            uint32_t bf[4][2];
#pragma unroll
            for (int ntp = 0; ntp < 2; ntp++) {
                uint32_t r[4];
                uint32_t addr = bB + (uint32_t)(((ks * 16 + (lane & 15)) * KPB_STR
                               + wn * 32 + ntp * 16 + ((lane >> 4) << 3)) * 2);
                ldsm_x4_t(r, addr);
                bf[2 * ntp][0]     = r[0];
                bf[2 * ntp][1]     = r[1];
                bf[2 * ntp + 1][0] = r[2];
                bf[2 * ntp + 1][1] = r[3];
            }
#pragma unroll
            for (int mt = 0; mt < 4; mt++) {
                uint32_t af[4];
                uint32_t addr = aB + (uint32_t)(((wm * 64 + mt * 16 + (lane & 15)) * KPA_STR
                               + ks * 16 + ((lane >> 4) << 3)) * 2);
                ldsm_x4(af, addr);
#pragma unroll
                for (int nt = 0; nt < 4; nt++)
                    mma_f16(acc[mt][nt], af, bf[nt]);
            }
        }
        scur++; if (scur >= KP_STG) scur -= KP_STG;
        __syncthreads();
    }

    __half* Op = out + (size_t)z * Mtot * DHEAD;
#pragma unroll
    for (int mt = 0; mt < 4; mt++) {
        const int r = m0 + wm * 64 + mt * 16 + (lane >> 2);
#pragma unroll
        for (int nt = 0; nt < 4; nt++) {
            const int c = wn * 32 + nt * 8 + ((lane & 3) << 1);
            float b0 = bias[z * DHEAD + c], b1 = bias[z * DHEAD + c + 1];
            *(__half2*)(Op + (size_t)r * DHEAD + c) =
                __floats2half2_rn(acc[mt][nt][0] + b0, acc[mt][nt][1] + b1);
            *(__half2*)(Op + (size_t)(r + 8) * DHEAD + c) =
                __floats2half2_rn(acc[mt][nt][2] + b0, acc[mt][nt][3] + b1);
        }
    }
}

// ===========================================================================
// Scores on fp16 tensor cores (NT) + fp32 exp; writes fp16 e + colsum.
// ===========================================================================
#define SC_STR 136
#define SC_SMEM (2 * 128 * SC_STR * 2)

__global__ void __launch_bounds__(256, 2)
scores_f16_kernel(float scale)
{
    extern __shared__ __half scs[];
    const uint32_t sA = (uint32_t)__cvta_generic_to_shared(scs);
    const uint32_t sB = sA + 128 * SC_STR * 2;
    __shared__ float red[16][128];

    const int tid  = threadIdx.x;
    const int lane = tid & 31;
    const int wid  = tid >> 5;
    const int wm   = wid >> 2;
    const int wn   = wid & 3;
    const int z    = blockIdx.z;
    const int m0   = blockIdx.y * 128;
    const int n0   = blockIdx.x * 128;

    const __half* Ap = g_Sh + (size_t)z * NSENT * DHEAD + (size_t)m0 * DHEAD;
    const __half* Bp = g_Kh + (size_t)z * NKNOW * DHEAD + (size_t)n0 * DHEAD;

    {
        const int r  = tid >> 1;
        const int c0 = (tid & 1) << 6;
#pragma unroll
        for (int i = 0; i < 8; i++) {
            cp_async16(sA + (uint32_t)(r * SC_STR + c0 + 8 * i) * 2,
                       Ap + (size_t)r * DHEAD + c0 + 8 * i);
            cp_async16(sB + (uint32_t)(r * SC_STR + c0 + 8 * i) * 2,
                       Bp + (size_t)r * DHEAD + c0 + 8 * i);
        }
        asm volatile("cp.async.commit_group;" ::: "memory");
        asm volatile("cp.async.wait_group 0;" ::: "memory");
        __syncthreads();
    }

    float acc[4][4][4];
#pragma unroll
    for (int mt = 0; mt < 4; mt++)
#pragma unroll
        for (int nt = 0; nt < 4; nt++)
#pragma unroll
            for (int r = 0; r < 4; r++) acc[mt][nt][r] = 0.f;

#pragma unroll
    for (int ks = 0; ks < 8; ks++) {
        uint32_t bf[4][2];
#pragma unroll
        for (int ntp = 0; ntp < 2; ntp++) {
            uint32_t r[4];
            uint32_t addr = sB + (uint32_t)(((wn * 32 + ntp * 16 + (lane & 15)) * SC_STR
                           + ks * 16 + ((lane >> 4) << 3)) * 2);
            ldsm_x4(r, addr);
            bf[2 * ntp][0]     = r[0];
            bf[2 * ntp][1]     = r[2];
            bf[2 * ntp + 1][0] = r[1];
            bf[2 * ntp + 1][1] = r[3];
        }
#pragma unroll
        for (int mt = 0; mt < 4; mt++) {
            uint32_t af[4];
            uint32_t addr = sA + (uint32_t)(((wm * 64 + mt * 16 + (lane & 15)) * SC_STR
                           + ks * 16 + ((lane >> 4) << 3)) * 2);
            ldsm_x4(af, addr);
#pragma unroll
            for (int nt = 0; nt < 4; nt++)
                mma_f16(acc[mt][nt], af, bf[nt]);
        }
    }

    // epilogue: exp (fp32), write fp16 e, column partial sums
    float cp[8];
#pragma unroll
    for (int j = 0; j < 8; j++) cp[j] = 0.f;
    __half* Ep = g_Ah + (size_t)z * NSENT * NKNOW;
#pragma unroll
    for (int mt = 0; mt < 4; mt++) {
        const int r = m0 + wm * 64 + mt * 16 + (lane >> 2);
#pragma unroll
        for (int nt = 0; nt < 4; nt++) {
            const int c = n0 + wn * 32 + nt * 8 + ((lane & 3) << 1);
            float e0 = __expf(acc[mt][nt][0] * scale);
            float e1 = __expf(acc[mt][nt][1] * scale);
            float e2 = __expf(acc[mt][nt][2] * scale);
            float e3 = __expf(acc[mt][nt][3] * scale);
            *(__half2*)(Ep + (size_t)r * NKNOW + c)       = __floats2half2_rn(e0, e1);
            *(__half2*)(Ep + (size_t)(r + 8) * NKNOW + c) = __floats2half2_rn(e2, e3);
            cp[nt * 2]     += e0 + e2;
            cp[nt * 2 + 1] += e1 + e3;
        }
    }
    const int rr = wm * 8 + (lane >> 2);
#pragma unroll
    for (int nt = 0; nt < 4; nt++) {
        red[rr][wn * 32 + nt * 8 + ((lane & 3) << 1)]     = cp[nt * 2];
        red[rr][wn * 32 + nt * 8 + ((lane & 3) << 1) + 1] = cp[nt * 2 + 1];
    }
    __syncthreads();
    if (tid < 128) {
        float s = 0.f;
#pragma unroll
        for (int r = 0; r < 16; r++) s += red[r][tid];
        atomicAdd(&g_colsum[(size_t)z * NKNOW + n0 + tid], s);
    }
}

// ===========================================================================
// Normalize: read fp16 e, write fp32 attn = e*inv and fp16 normalized copy.
// ===========================================================================
__global__ __launch_bounds__(256)
void normalize_kernel(float* __restrict__ attn)
{
    const int h = blockIdx.z;
    const int m = blockIdx.x * 256 + threadIdx.x;
    const int n0 = blockIdx.y * 64;
    const float iv = 1.f / g_colsum[(size_t)h * NKNOW + m];
    const size_t base = (size_t)h * NSENT * NKNOW + (size_t)n0 * NKNOW + m;
    float*  p   = attn + base;
    __half* p16 = g_Ah + base;
#pragma unroll 4
    for (int nn = 0; nn < 64; nn++) {
        size_t idx = (size_t)nn * NKNOW;
        float v = __half2float(p16[idx]) * iv;
        p[idx]   = v;
        p16[idx] = __float2half_rn(v);
    }
}

// ===========================================================================
// fused = attn_h16 @ knowledge_h16 (fp16 mma, fp32 accum)
//   CTA 128x256xK64, 512 thr (16 warps 4x4, warp 32x64), 3-stage cp.async
// ===========================================================================
#define FBM 128
#define FBN 256
#define FBK 64
#define FSTG 3
#define SA_STR 72
#define SB_STR 264
#define SA_H (FBM * SA_STR)            // 9216 halves/stage
#define SB_H (FBK * SB_STR)            // 16896 halves/stage
#define FSMEM (FSTG * (SA_H + SB_H) * 2)   // 156672 B

__global__ void __launch_bounds__(512, 1)
fused_mma_f16(float* __restrict__ C)
{
    extern __shared__ __half smh[];
    const uint32_t sA_u32 = (uint32_t)__cvta_generic_to_shared(smh);
    const uint32_t sB_u32 = sA_u32 + FSTG * SA_H * 2;

    const int tid  = threadIdx.x;
    const int lane = tid & 31;
    const int wid  = tid >> 5;
    const int wm   = wid & 3;
    const int wn   = wid >> 2;
    const int z    = blockIdx.z;
    const int m0   = blockIdx.y * FBM;
    const int n0   = blockIdx.x * FBN;

    const __half* Ap = g_Ah + (size_t)z * NSENT * NKNOW + (size_t)m0 * NKNOW;
    const __half* Bp = g_Bh + n0;

    const int a_row  = tid >> 2;            // 0..127
    const int a_ch   = (tid & 3) << 3;      // 0..24
    const int b_row0 = tid >> 5;            // 0..15
    const int b_ch0  = (tid & 31) << 3;     // 0..248

    float acc[2][8][4];
#pragma unroll
    for (int mt = 0; mt < 2; mt++)
#pragma unroll
        for (int nt = 0; nt < 8; nt++)
#pragma unroll
            for (int r = 0; r < 4; r++) acc[mt][nt][r] = 0.f;

    const int NT = NKNOW / FBK;             // 128

    auto issue = [&](int kt, int s) {
        const __half* abase = Ap + (size_t)kt * FBK;
#pragma unroll
        for (int i = 0; i < 2; i++)
            cp_async16(sA_u32 + (uint32_t)(s * SA_H + a_row * SA_STR + a_ch + 32 * i) * 2,
                       abase + (size_t)a_row * NKNOW + a_ch + 32 * i);
        const __half* bbase = Bp + (size_t)(kt * FBK) * KFDIM;
#pragma unroll
        for (int p = 0; p < 4; p++) {
            int row = b_row0 + p * 16;
            cp_async16(sB_u32 + (uint32_t)(s * SB_H + row * SB_STR + b_ch0) * 2,
                       bbase + (size_t)row * KFDIM + b_ch0);
        }
        asm volatile("cp.async.commit_group;" ::: "memory");
    };

    issue(0, 0); issue(1, 1);

    int scur = 0;
    for (int kt = 0; kt < NT; kt++) {
        if (kt + 1 < NT) asm volatile("cp.async.wait_group 1;" ::: "memory");
        else             asm volatile("cp.async.wait_group 0;" ::: "memory");
        __syncthreads();

        if (kt + 2 < NT) {
            int snx = scur + 2; if (snx >= FSTG) snx -= FSTG;
            issue(kt + 2, snx);
        }

        const uint32_t aBase = sA_u32 + (uint32_t)(scur * SA_H) * 2;
        const uint32_t bBase = sB_u32 + (uint32_t)(scur * SB_H) * 2;

#pragma unroll
        for (int ks = 0; ks < 4; ks++) {
            uint32_t bf[8][2];
#pragma unroll
            for (int ntp = 0; ntp < 4; ntp++) {
                uint32_t r[4];
                uint32_t addr = bBase + (uint32_t)(((ks * 16 + (lane & 15)) * SB_STR
                               + wn * 64 + ntp * 16 + ((lane >> 4) << 3)) * 2);
                ldsm_x4_t(r, addr);
                bf[2 * ntp][0]     = r[0];
                bf[2 * ntp][1]     = r[1];
                bf[2 * ntp + 1][0] = r[2];
                bf[2 * ntp + 1][1] = r[3];
            }
#pragma unroll
            for (int mt = 0; mt < 2; mt++) {
                uint32_t af[4];
                uint32_t addr = aBase + (uint32_t)(((wm * 32 + mt * 16 + (lane & 15)) * SA_STR
                               + ks * 16 + ((lane >> 4) << 3)) * 2);
                ldsm_x4(af, addr);
#pragma unroll
                for (int nt = 0; nt < 8; nt++)
                    mma_f16(acc[mt][nt], af, bf[nt]);
            }
        }
        scur++; if (scur >= FSTG) scur -= FSTG;
    }

    const int ldc = NHEADS * KFDIM;
#pragma unroll
    for (int mt = 0; mt < 2; mt++) {
        const int r = m0 + wm * 32 + mt * 16 + (lane >> 2);
#pragma unroll
        for (int nt = 0; nt < 8; nt++) {
            const int c = z * KFDIM + n0 + wn * 64 + nt * 8 + ((lane & 3) << 1);
            *(float2*)(C + (size_t)r * ldc + c)       = make_float2(acc[mt][nt][0], acc[mt][nt][1]);
            *(float2*)(C + (size_t)(r + 8) * ldc + c) = make_float2(acc[mt][nt][2], acc[mt][nt][3]);
        }
    }
}

// ===========================================================================
// Host side
// ===========================================================================
extern "C" void kernel_launch(void* const* d_in, const int* in_sizes, int n_in,
                              void* d_out, int out_size)
{
    const float* sentences = (const float*)d_in[0];
    const float* knowledge = (const float*)d_in[1];
    const float* w_s       = (const float*)d_in[2];
    const float* b_s       = (const float*)d_in[3];
    const float* w_k       = (const float*)d_in[4];
    const float* b_k       = (const float*)d_in[5];

    float* attn  = (float*)d_out;
    float* fused = (float*)d_out + (size_t)NHEADS * NSENT * NKNOW;

    float* csum = nullptr;
    __half *snth = nullptr, *wsh = nullptr, *Sh = nullptr, *Kh = nullptr,
           *wkh = nullptr, *Bh = nullptr;
    cudaGetSymbolAddress((void**)&csum, g_colsum);
    cudaGetSymbolAddress((void**)&snth, g_snth);
    cudaGetSymbolAddress((void**)&wsh,  g_wsh);
    cudaGetSymbolAddress((void**)&Sh,   g_Sh);
    cudaGetSymbolAddress((void**)&Kh,   g_Kh);
    cudaGetSymbolAddress((void**)&wkh,  g_wkh);
    cudaGetSymbolAddress((void**)&Bh,   g_Bh);

    static bool attrs_set = false;
    if (!attrs_set) {
        cudaFuncSetAttribute(proj_f16_kernel,
                             cudaFuncAttributeMaxDynamicSharedMemorySize, KPSMEM);
        cudaFuncSetAttribute(scores_f16_kernel,
                             cudaFuncAttributeMaxDynamicSharedMemorySize, SC_SMEM);
        cudaFuncSetAttribute(fused_mma_f16,
                             cudaFuncAttributeMaxDynamicSharedMemorySize, FSMEM);
        attrs_set = true;
    }

    // 0) zero colsums; fp16 conversions
    cudaMemsetAsync(csum, 0, (size_t)NHEADS * NKNOW * sizeof(float));
    cvt_f16_kernel<<<((size_t)NKNOW * KFDIM) / 1024, 256>>>(knowledge, Bh);
    cvt_f16_kernel<<<((size_t)NHEADS * KFDIM * DHEAD) / 1024, 256>>>(w_k, wkh);
    cvt_f16_kernel<<<((size_t)NSENT * DMODEL) / 1024, 256>>>(sentences, snth);
    cvt_f16_kernel<<<((size_t)NHEADS * DMODEL * DHEAD) / 1024, 256>>>(w_s, wsh);

    // 1) S projection (fp16 mma)
    {
        dim3 grid(1, NSENT / 128, NHEADS);
        proj_f16_kernel<<<grid, 256, KPSMEM>>>(snth, wsh, b_s, Sh, DMODEL, NSENT);
    }
    // 2) K projection (fp16 mma)
    {
        dim3 grid(1, NKNOW / 128, NHEADS);
        proj_f16_kernel<<<grid, 256, KPSMEM>>>(Bh, wkh, b_k, Kh, KFDIM, NKNOW);
    }
    // 3) scores + exp -> fp16 e + colsum
    {
        dim3 grid(NKNOW / 128, NSENT / 128, NHEADS);
        scores_f16_kernel<<<grid, 256, SC_SMEM>>>(0.08838834764831845f);
    }
    // 4) normalize: fp32 attn output + normalized fp16
    {
        dim3 grid(NKNOW / 256, NSENT / 64, NHEADS);
        normalize_kernel<<<grid, 256>>>(attn);
    }
    // 5) fused GEMM (fp16 mma, K-chunk 64, 3-stage)
    {
        dim3 grid(KFDIM / FBN, NSENT / FBM, NHEADS);
        fused_mma_f16<<<grid, 512, FSMEM>>>(fused);
    }
}